// round 14
// baseline (speedup 1.0000x reference)
#include <cuda_runtime.h>
#include <cuda_fp16.h>
#include <math.h>
#include <stdint.h>

#define B_  2
#define T_  2048
#define E_  1024
#define H_  16
#define HS_ 64
#define NROWS (B_*T_)   // 4096 rows
#define FF  (4*E_)      // 4096

// ---------------- scratch ----------------------------------------------------
__device__ __half g_h16  [NROWS * E_];      // LN1 output (fp16)
__device__ __half g_wqkv16[E_ * 3 * E_];    // repacked QKV weights [E,3E] fp16
__device__ __half g_wp16 [E_ * E_];
__device__ __half g_w116 [E_ * FF];
__device__ __half g_w216 [FF * E_];
__device__ __half g_qkv16[NROWS * 3 * E_];  // Q|K|V fp16
__device__ __half g_attn16[NROWS * E_];     // attention out fp16
__device__ float  g_x1   [NROWS * E_];      // residual 1 (fp32)
__device__ __half g_h2_16[NROWS * E_];      // LN2 output fp16
__device__ __half g_ff116[NROWS * FF];      // FFN hidden fp16
__device__ float  g_psum [2 * NROWS * E_];  // split-K partials (fp32)

__device__ __forceinline__ void cp_async16(uint32_t dst, const void* src) {
    asm volatile("cp.async.cg.shared.global [%0], [%1], 16;" :: "r"(dst), "l"(src));
}
__device__ __forceinline__ uint32_t smem_u32(const void* p) {
    uint32_t a;
    asm("{ .reg .u64 t; cvta.to.shared.u64 t, %1; cvt.u32.u64 %0, t; }" : "=r"(a) : "l"(p));
    return a;
}
// D += A*B, m16n8k16 fp16 inputs, fp32 accum
__device__ __forceinline__ void mma16(float* c, const uint32_t* a, uint32_t b0, uint32_t b1) {
    asm volatile("mma.sync.aligned.m16n8k16.row.col.f32.f16.f16.f32 "
        "{%0,%1,%2,%3}, {%4,%5,%6,%7}, {%8,%9}, {%0,%1,%2,%3};"
        : "+f"(c[0]), "+f"(c[1]), "+f"(c[2]), "+f"(c[3])
        : "r"(a[0]), "r"(a[1]), "r"(a[2]), "r"(a[3]), "r"(b0), "r"(b1));
}
__device__ __forceinline__ void ldsm4(uint32_t* r, uint32_t a) {
    asm volatile("ldmatrix.sync.aligned.m8n8.x4.shared.b16 {%0,%1,%2,%3}, [%4];"
        : "=r"(r[0]), "=r"(r[1]), "=r"(r[2]), "=r"(r[3]) : "r"(a));
}
__device__ __forceinline__ void ldsm4t(uint32_t* r, uint32_t a) {
    asm volatile("ldmatrix.sync.aligned.m8n8.x4.trans.shared.b16 {%0,%1,%2,%3}, [%4];"
        : "=r"(r[0]), "=r"(r[1]), "=r"(r[2]), "=r"(r[3]) : "r"(a));
}

// ---------------- LayerNorm (fp32 in -> fp16 out) ----------------------------
__global__ __launch_bounds__(256) void ln_kernel(const float* __restrict__ x,
                                                 const float* __restrict__ g,
                                                 const float* __restrict__ b,
                                                 __half* __restrict__ out)
{
    int row = blockIdx.x;
    int tid = threadIdx.x;
    const float4* xr = reinterpret_cast<const float4*>(x + (size_t)row * E_);
    float4 v = xr[tid];
    float s  = v.x + v.y + v.z + v.w;
    float sq = v.x*v.x + v.y*v.y + v.z*v.z + v.w*v.w;

    __shared__ float sh[16];
    __shared__ float s_mu, s_rs;
    #pragma unroll
    for (int o = 16; o > 0; o >>= 1) {
        s  += __shfl_down_sync(0xffffffffu, s,  o);
        sq += __shfl_down_sync(0xffffffffu, sq, o);
    }
    int lane = tid & 31, wid = tid >> 5;
    if (lane == 0) { sh[wid] = s; sh[8 + wid] = sq; }
    __syncthreads();
    if (tid == 0) {
        float ts = 0.f, tq = 0.f;
        #pragma unroll
        for (int w = 0; w < 8; w++) { ts += sh[w]; tq += sh[8 + w]; }
        float mu  = ts * (1.0f / E_);
        float var = tq * (1.0f / E_) - mu * mu;
        s_mu = mu;
        s_rs = rsqrtf(var + 1e-5f);
    }
    __syncthreads();
    float mu = s_mu, rs = s_rs;
    float4 gg = reinterpret_cast<const float4*>(g)[tid];
    float4 bb = reinterpret_cast<const float4*>(b)[tid];
    __half2 h0 = __floats2half2_rn((v.x - mu) * rs * gg.x + bb.x,
                                   (v.y - mu) * rs * gg.y + bb.y);
    __half2 h1 = __floats2half2_rn((v.z - mu) * rs * gg.z + bb.z,
                                   (v.w - mu) * rs * gg.w + bb.w);
    __half2* op = reinterpret_cast<__half2*>(out + (size_t)row * E_ + tid * 4);
    op[0] = h0; op[1] = h1;
}

// ---------------- fused fp32 -> fp16 convert for 3 weights -------------------
__device__ __forceinline__ void cvt8(const float* ip, __half* op) {
    const float4* p = reinterpret_cast<const float4*>(ip);
    float4 a = p[0], b = p[1];
    __half2 h[4] = { __floats2half2_rn(a.x, a.y), __floats2half2_rn(a.z, a.w),
                     __floats2half2_rn(b.x, b.y), __floats2half2_rn(b.z, b.w) };
    *reinterpret_cast<float4*>(op) = *reinterpret_cast<float4*>(h);
}
__global__ void f2h3_kernel(const float* __restrict__ a, __half* __restrict__ oa,
                            const float* __restrict__ b, __half* __restrict__ ob,
                            const float* __restrict__ c, __half* __restrict__ oc,
                            int na8, int nb8, int nc8)
{
    int i = blockIdx.x * blockDim.x + threadIdx.x;
    if (i < na8)                 { cvt8(a + 8 * (size_t)i, oa + 8 * (size_t)i); return; }
    i -= na8;
    if (i < nb8)                 { cvt8(b + 8 * (size_t)i, ob + 8 * (size_t)i); return; }
    i -= nb8;
    if (i < nc8)                 { cvt8(c + 8 * (size_t)i, oc + 8 * (size_t)i); }
}

// ---------------- Repack Wq/Wk/Wv [H,E,HS] -> [E, 3E] fp16 (4/thread) --------
__global__ void repack_kernel(const float* __restrict__ Wq,
                              const float* __restrict__ Wk,
                              const float* __restrict__ Wv,
                              __half* __restrict__ Wqkv)
{
    int i = blockIdx.x * blockDim.x + threadIdx.x;   // over H*E*HS/4
    if (i >= H_ * E_ * HS_ / 4) return;
    int h = i / (E_ * HS_ / 4);
    int r = i % (E_ * HS_ / 4);
    int e = r / (HS_ / 4);
    int d4 = (r % (HS_ / 4)) * 4;
    int col = h * HS_ + d4;
    size_t base = (size_t)e * (3 * E_);
    size_t src = (size_t)i * 4;
    float4 q = *reinterpret_cast<const float4*>(Wq + src);
    float4 k = *reinterpret_cast<const float4*>(Wk + src);
    float4 v = *reinterpret_cast<const float4*>(Wv + src);
    __half2 qh[2] = { __floats2half2_rn(q.x, q.y), __floats2half2_rn(q.z, q.w) };
    __half2 kh[2] = { __floats2half2_rn(k.x, k.y), __floats2half2_rn(k.z, k.w) };
    __half2 vh[2] = { __floats2half2_rn(v.x, v.y), __floats2half2_rn(v.z, v.w) };
    *reinterpret_cast<float2*>(Wqkv + base + col)           = *reinterpret_cast<float2*>(qh);
    *reinterpret_cast<float2*>(Wqkv + base + E_ + col)      = *reinterpret_cast<float2*>(kh);
    *reinterpret_cast<float2*>(Wqkv + base + 2 * E_ + col)  = *reinterpret_cast<float2*>(vh);
}

// ---------------- final fused add: out = x1 + p0 + p1 + b2 -------------------
__global__ __launch_bounds__(256) void add4_kernel(const float* __restrict__ x1,
                                                   const float* __restrict__ p0,
                                                   const float* __restrict__ p1,
                                                   const float* __restrict__ b2,
                                                   float* __restrict__ out)
{
    int i = blockIdx.x * blockDim.x + threadIdx.x;      // over NROWS*E_/4
    int c4 = i & (E_ / 4 - 1);
    float4 a = reinterpret_cast<const float4*>(x1)[i];
    float4 q = reinterpret_cast<const float4*>(p0)[i];
    float4 r = reinterpret_cast<const float4*>(p1)[i];
    float4 bb = reinterpret_cast<const float4*>(b2)[c4];
    float4 o;
    o.x = a.x + q.x + r.x + bb.x;
    o.y = a.y + q.y + r.y + bb.y;
    o.z = a.z + q.z + r.z + bb.z;
    o.w = a.w + q.w + r.w + bb.w;
    reinterpret_cast<float4*>(out)[i] = o;
}

// ---------------- raw-mma fp16 GEMM (m16n8k16, fp32 accum, BK=64) ------------
// 128 threads = 4 warps; CTA tile 128x128; warp tile 64x64.
// ONE barrier per chunk: wait_group -> sync -> issue(c+2) -> compute(c).
// Optional split-K via gridDim.z (lda decouples A row stride from K).
#define BM   128
#define BN   128
#define BKC  64
#define ASTH 72                       // A row stride (halves): 144B = 9x16B (odd)
#define BSTH 136                      // B row stride (halves): 272B = 17x16B (odd)
#define STAGE_H (BM*ASTH + BKC*BSTH)  // 17920 halves / stage
#define NSTG 3
#define GSMEM (NSTG * STAGE_H * 2)    // 107520 B -> 2 CTAs/SM

__global__ __launch_bounds__(128, 2) void h16_gemm(
    const __half* __restrict__ A, const __half* __restrict__ Bm,
    float* __restrict__ C, __half* __restrict__ Ch, int M, int N, int K, int lda,
    const float* __restrict__ bias, const float* __restrict__ res, int relu)
{
    // split-K offsets (gridDim.z > 1)
    if (blockIdx.z) {
        A  += (size_t)blockIdx.z * K;           // column offset within row (lda = full K)
        Bm += (size_t)blockIdx.z * K * N;       // row offset in B
        C  += (size_t)blockIdx.z * M * N;       // partial output buffer
    }

    extern __shared__ __half smh[];
    uint32_t smb = smem_u32(smh);

    int tid  = threadIdx.x;
    int wid  = tid >> 5, lane = tid & 31;
    int wm   = wid & 1;           // 64-row slab
    int wn   = wid >> 1;          // 0..1 -> 64-col slab
    int gid  = lane >> 2, tig = lane & 3;
    int g8   = lane >> 3, i8 = lane & 7;
    int m0   = blockIdx.y * BM;
    int n0   = blockIdx.x * BN;
    int NC   = K / BKC;

    int rowA = ((g8 & 1) << 3) + i8;      // A (non-trans)
    int colA = (g8 >> 1) << 3;            // k offset 0/8
    int rowB = ((g8 & 1) << 3) + i8;      // B (trans): k rows
    int colB = (g8 >> 1) << 3;            // n offset 0/8

    float acc[4][8][4];
    #pragma unroll
    for (int mt = 0; mt < 4; mt++)
        #pragma unroll
        for (int nt = 0; nt < 8; nt++)
            #pragma unroll
            for (int r = 0; r < 4; r++) acc[mt][nt][r] = 0.f;

    auto issue = [&](int c) {
        int buf = c % NSTG;
        uint32_t stA = smb + (uint32_t)(buf * STAGE_H) * 2u;
        uint32_t stB = stA + (uint32_t)(BM * ASTH) * 2u;
        int k0 = c * BKC;
        #pragma unroll
        for (int t = 0; t < 8; t++) {
            int idx = tid + t * 128;
            int r  = idx >> 3;            // 0..127
            int kk = (idx & 7) * 8;       // halves 0..56
            cp_async16(stA + (uint32_t)(r * ASTH + kk) * 2u,
                       A + (size_t)(m0 + r) * lda + k0 + kk);
        }
        #pragma unroll
        for (int t = 0; t < 8; t++) {
            int idx = tid + t * 128;
            int r  = idx >> 4;            // 0..63
            int nn = (idx & 15) * 8;      // halves 0..120
            cp_async16(stB + (uint32_t)(r * BSTH + nn) * 2u,
                       Bm + (size_t)(k0 + r) * N + n0 + nn);
        }
        asm volatile("cp.async.commit_group;" ::: "memory");
    };

    issue(0);
    issue(1);

    for (int c = 0; c < NC; c++) {
        if (c + 1 < NC) { asm volatile("cp.async.wait_group 1;" ::: "memory"); }
        else            { asm volatile("cp.async.wait_group 0;" ::: "memory"); }
        __syncthreads();                       // publish stage c; retire stage c-1
        if (c + 2 < NC) issue(c + 2);          // safe: all warps done with stage (c+2)%3

        uint32_t sA = smb + (uint32_t)((c % NSTG) * STAGE_H) * 2u;
        uint32_t sB = sA + (uint32_t)(BM * ASTH) * 2u;

        #pragma unroll
        for (int kk = 0; kk < 4; kk++) {
            uint32_t af[4][4];
            #pragma unroll
            for (int mt = 0; mt < 4; mt++)
                ldsm4(af[mt], sA + (uint32_t)((wm * 64 + mt * 16 + rowA) * ASTH
                                              + kk * 16 + colA) * 2u);
            uint32_t bf[8][2];
            #pragma unroll
            for (int g = 0; g < 4; g++) {
                uint32_t vf[4];
                ldsm4t(vf, sB + (uint32_t)((kk * 16 + rowB) * BSTH
                                           + wn * 64 + g * 16 + colB) * 2u);
                bf[2 * g][0] = vf[0]; bf[2 * g][1] = vf[1];
                bf[2 * g + 1][0] = vf[2]; bf[2 * g + 1][1] = vf[3];
            }
            #pragma unroll
            for (int mt = 0; mt < 4; mt++)
                #pragma unroll
                for (int nt = 0; nt < 8; nt++)
                    mma16(acc[mt][nt], af[mt], bf[nt][0], bf[nt][1]);
        }
    }

    // ---- direct register epilogue ----
    #pragma unroll
    for (int mt = 0; mt < 4; mt++) {
        size_t row0 = (size_t)(m0 + wm * 64 + mt * 16 + gid);
        size_t row1 = row0 + 8;
        #pragma unroll
        for (int nt = 0; nt < 8; nt++) {
            int col = n0 + wn * 64 + nt * 8 + 2 * tig;
            float c0 = acc[mt][nt][0], c1 = acc[mt][nt][1];
            float c2 = acc[mt][nt][2], c3 = acc[mt][nt][3];
            if (bias) {
                float2 bb = *reinterpret_cast<const float2*>(bias + col);
                c0 += bb.x; c1 += bb.y; c2 += bb.x; c3 += bb.y;
            }
            if (relu) {
                c0 = fmaxf(c0, 0.f); c1 = fmaxf(c1, 0.f);
                c2 = fmaxf(c2, 0.f); c3 = fmaxf(c3, 0.f);
            }
            if (res) {
                float2 r0v = *reinterpret_cast<const float2*>(res + row0 * N + col);
                float2 r1v = *reinterpret_cast<const float2*>(res + row1 * N + col);
                c0 += r0v.x; c1 += r0v.y; c2 += r1v.x; c3 += r1v.y;
            }
            if (Ch) {
                *reinterpret_cast<__half2*>(Ch + row0 * N + col) = __floats2half2_rn(c0, c1);
                *reinterpret_cast<__half2*>(Ch + row1 * N + col) = __floats2half2_rn(c2, c3);
            } else {
                *reinterpret_cast<float2*>(C + row0 * N + col) = make_float2(c0, c1);
                *reinterpret_cast<float2*>(C + row1 * N + col) = make_float2(c2, c3);
            }
        }
    }
}

// ---------------- fp16 tensor-core causal flash attention --------------------
// (unchanged — register P, ldmatrix K/V)
#define APH 72

__global__ __launch_bounds__(128) void attn_kernel(const __half* __restrict__ qkv,
                                                   __half* __restrict__ out)
{
    __shared__ __half asm16[4 * 64 * APH];
    uint32_t smu = smem_u32(asm16);

    int tid = threadIdx.x, w = tid >> 5, lane = tid & 31;
    int gid = lane >> 2, tig = lane & 3;
    int g8  = lane >> 3, i8 = lane & 7;
    int qt = (T_ / 64 - 1) - blockIdx.x;
    int bh = blockIdx.y, b = bh >> 4, h = bh & 15;

    int rowK = ((g8 >> 1) << 3) + i8;
    int colK = (g8 & 1) << 3;
    int rowV = ((g8 & 1) << 3) + i8;
    int colV = (g8 >> 1) << 3;

    uint32_t qa[4][4];
    {
        const __half2 sc2 = __floats2half2_rn(0.125f, 0.125f);
        #pragma unroll
        for (int ks = 0; ks < 4; ks++)
            #pragma unroll
            for (int r = 0; r < 4; r++) {
                int row = w * 16 + gid + (r & 1) * 8;
                int col = ks * 16 + 2 * tig + ((r >> 1) * 8);
                __half2 v = *reinterpret_cast<const __half2*>(
                    qkv + (size_t)(b * T_ + qt * 64 + row) * (3 * E_) + h * HS_ + col);
                v = __hmul2(v, sc2);
                qa[ks][r] = *reinterpret_cast<uint32_t*>(&v);
            }
    }

    float oa[8][4];
    #pragma unroll
    for (int nt = 0; nt < 8; nt++)
        #pragma unroll
        for (int r = 0; r < 4; r++) oa[nt][r] = 0.f;
    float m0 = -1e30f, m1 = -1e30f, l0 = 0.f, l1 = 0.f;

    auto loadKV = [&](int kt, int bu) {
        const __half* kb = qkv + (size_t)(b * T_ + kt * 64) * (3 * E_) + E_ + h * HS_;
        const __half* vb = kb + E_;
        uint32_t kbase = smu + (uint32_t)(bu * 64 * APH) * 2u;
        uint32_t vbase = smu + (uint32_t)((2 + bu) * 64 * APH) * 2u;
        #pragma unroll
        for (int t = 0; t < 4; t++) {
            int i = tid + t * 128;
            int r = i >> 3, c = (i & 7) * 8;
            cp_async16(kbase + (uint32_t)(r * APH + c) * 2u, kb + (size_t)r * (3 * E_) + c);
            cp_async16(vbase + (uint32_t)(r * APH + c) * 2u, vb + (size_t)r * (3 * E_) + c);
        }
        asm volatile("cp.async.commit_group;" ::: "memory");
    };

    loadKV(0, 0);

    for (int kt = 0; kt <= qt; kt++) {
        int bu = kt & 1;
        if (kt < qt) {
            loadKV(kt + 1, bu ^ 1);
            asm volatile("cp.async.wait_group 1;" ::: "memory");
        } else {
            asm volatile("cp.async.wait_group 0;" ::: "memory");
        }
        __syncthreads();

        uint32_t kbase = smu + (uint32_t)(bu * 64 * APH) * 2u;
        uint32_t vbase = smu + (uint32_t)((2 + bu) * 64 * APH) * 2u;

        float sa[8][4];
        #pragma unroll
        for (int nt = 0; nt < 8; nt++)
            #pragma unroll
            for (int r = 0; r < 4; r++) sa[nt][r] = 0.f;

        #pragma unroll
        for (int ks = 0; ks < 4; ks++) {
            #pragma unroll
            for (int ntp = 0; ntp < 4; ntp++) {
                uint32_t kf[4];
                ldsm4(kf, kbase + (uint32_t)((ntp * 16 + rowK) * APH + ks * 16 + colK) * 2u);
                mma16(sa[2 * ntp],     qa[ks], kf[0], kf[1]);
                mma16(sa[2 * ntp + 1], qa[ks], kf[2], kf[3]);
            }
        }

        if (kt == qt) {
            int r0 = w * 16 + gid, r1 = r0 + 8;
            #pragma unroll
            for (int nt = 0; nt < 8; nt++) {
                int c0 = nt * 8 + 2 * tig, c1 = c0 + 1;
                if (c0 > r0) sa[nt][0] = -1e30f;
                if (c1 > r0) sa[nt][1] = -1e30f;
                if (c0 > r1) sa[nt][2] = -1e30f;
                if (c1 > r1) sa[nt][3] = -1e30f;
            }
        }

        float mt0 = -1e30f, mt1 = -1e30f;
        #pragma unroll
        for (int nt = 0; nt < 8; nt++) {
            mt0 = fmaxf(mt0, fmaxf(sa[nt][0], sa[nt][1]));
            mt1 = fmaxf(mt1, fmaxf(sa[nt][2], sa[nt][3]));
        }
        mt0 = fmaxf(mt0, __shfl_xor_sync(0xffffffffu, mt0, 1));
        mt0 = fmaxf(mt0, __shfl_xor_sync(0xffffffffu, mt0, 2));
        mt1 = fmaxf(mt1, __shfl_xor_sync(0xffffffffu, mt1, 1));
        mt1 = fmaxf(mt1, __shfl_xor_sync(0xffffffffu, mt1, 2));

        float mn0 = fmaxf(m0, mt0), mn1 = fmaxf(m1, mt1);
        float cr0 = __expf(m0 - mn0), cr1 = __expf(m1 - mn1);
        m0 = mn0; m1 = mn1;

        float s0 = 0.f, s1 = 0.f;
        uint32_t ph0[8], ph1[8];
        #pragma unroll
        for (int nt = 0; nt < 8; nt++) {
            float e0 = __expf(sa[nt][0] - mn0), e1 = __expf(sa[nt][1] - mn0);
            float e2 = __expf(sa[nt][2] - mn1), e3 = __expf(sa[nt][3] - mn1);
            s0 += e0 + e1;  s1 += e2 + e3;
            __half2 hp0 = __floats2half2_rn(e0, e1);
            __half2 hp1 = __floats2half2_rn(e2, e3);
            ph0[nt] = *reinterpret_cast<uint32_t*>(&hp0);
            ph1[nt] = *reinterpret_cast<uint32_t*>(&hp1);
        }
        s0 += __shfl_xor_sync(0xffffffffu, s0, 1);
        s0 += __shfl_xor_sync(0xffffffffu, s0, 2);
        s1 += __shfl_xor_sync(0xffffffffu, s1, 1);
        s1 += __shfl_xor_sync(0xffffffffu, s1, 2);
        l0 = l0 * cr0 + s0;
        l1 = l1 * cr1 + s1;

        #pragma unroll
        for (int nt = 0; nt < 8; nt++) {
            oa[nt][0] *= cr0; oa[nt][1] *= cr0;
            oa[nt][2] *= cr1; oa[nt][3] *= cr1;
        }

        #pragma unroll
        for (int ks = 0; ks < 4; ks++) {
            uint32_t pa[4] = { ph0[2 * ks], ph1[2 * ks], ph0[2 * ks + 1], ph1[2 * ks + 1] };
            #pragma unroll
            for (int ntp = 0; ntp < 4; ntp++) {
                uint32_t vf[4];
                ldsm4t(vf, vbase + (uint32_t)((ks * 16 + rowV) * APH + ntp * 16 + colV) * 2u);
                mma16(oa[2 * ntp],     pa, vf[0], vf[1]);
                mma16(oa[2 * ntp + 1], pa, vf[2], vf[3]);
            }
        }
        __syncthreads();
    }

    float i0 = 1.f / l0, i1 = 1.f / l1;
    int r0 = qt * 64 + w * 16 + gid;
    #pragma unroll
    for (int nt = 0; nt < 8; nt++) {
        int col = h * HS_ + nt * 8 + 2 * tig;
        __half2* p0 = reinterpret_cast<__half2*>(out + (size_t)(b * T_ + r0) * E_ + col);
        __half2* p1 = reinterpret_cast<__half2*>(out + (size_t)(b * T_ + r0 + 8) * E_ + col);
        *p0 = __floats2half2_rn(oa[nt][0] * i0, oa[nt][1] * i0);
        *p1 = __floats2half2_rn(oa[nt][2] * i1, oa[nt][3] * i1);
    }
}

// ---------------- host -------------------------------------------------------
extern "C" void kernel_launch(void* const* d_in, const int* in_sizes, int n_in,
                              void* d_out, int out_size)
{
    const float* x   = (const float*)d_in[0];
    const float* Wq  = (const float*)d_in[1];
    const float* Wk  = (const float*)d_in[2];
    const float* Wv  = (const float*)d_in[3];
    const float* Wp  = (const float*)d_in[4];
    const float* bp  = (const float*)d_in[5];
    const float* W1  = (const float*)d_in[6];
    const float* b1  = (const float*)d_in[7];
    const float* W2  = (const float*)d_in[8];
    const float* b2  = (const float*)d_in[9];
    const float* g1  = (const float*)d_in[10];
    const float* be1 = (const float*)d_in[11];
    const float* g2  = (const float*)d_in[12];
    const float* be2 = (const float*)d_in[13];
    float* out = (float*)d_out;

    __half *h16, *wqkv16, *wp16, *w116, *w216, *qkv16, *attn16, *h2_16, *ff116;
    float *x1, *psum;
    cudaGetSymbolAddress((void**)&h16,    g_h16);
    cudaGetSymbolAddress((void**)&wqkv16, g_wqkv16);
    cudaGetSymbolAddress((void**)&wp16,   g_wp16);
    cudaGetSymbolAddress((void**)&w116,   g_w116);
    cudaGetSymbolAddress((void**)&w216,   g_w216);
    cudaGetSymbolAddress((void**)&qkv16,  g_qkv16);
    cudaGetSymbolAddress((void**)&attn16, g_attn16);
    cudaGetSymbolAddress((void**)&x1,     g_x1);
    cudaGetSymbolAddress((void**)&h2_16,  g_h2_16);
    cudaGetSymbolAddress((void**)&ff116,  g_ff116);
    cudaGetSymbolAddress((void**)&psum,   g_psum);

    cudaFuncSetAttribute(h16_gemm, cudaFuncAttributeMaxDynamicSharedMemorySize, GSMEM);

    // prep: LN1, repack, fused weight converts
    ln_kernel<<<NROWS, 256>>>(x, g1, be1, h16);
    repack_kernel<<<(H_ * E_ * HS_ / 4 + 255) / 256, 256>>>(Wq, Wk, Wv, wqkv16);
    {
        int na8 = E_ * E_ / 8, nb8 = E_ * FF / 8, nc8 = FF * E_ / 8;
        f2h3_kernel<<<(na8 + nb8 + nc8 + 255) / 256, 256>>>(
            Wp, wp16, W1, w116, W2, w216, na8, nb8, nc8);
    }

    // QKV = h @ Wqkv -> fp16
    h16_gemm<<<dim3(3*E_/BN, NROWS/BM), 128, GSMEM>>>(
        h16, wqkv16, nullptr, qkv16, NROWS, 3*E_, E_, E_, nullptr, nullptr, 0);
    // attention (fp16 tensor cores, register-resident P) -> fp16
    attn_kernel<<<dim3(T_/64, B_*H_), 128>>>(qkv16, attn16);
    // x1 = x + attn @ Wp + bp  (fp32 out)
    h16_gemm<<<dim3(E_/BN, NROWS/BM), 128, GSMEM>>>(
        attn16, wp16, x1, nullptr, NROWS, E_, E_, E_, bp, x, 0);
    // h2 = LN2(x1) -> fp16
    ln_kernel<<<NROWS, 256>>>(x1, g2, be2, h2_16);
    // ff1 = relu(h2 @ W1 + b1) -> fp16
    h16_gemm<<<dim3(FF/BN, NROWS/BM), 128, GSMEM>>>(
        h2_16, w116, nullptr, ff116, NROWS, FF, E_, E_, b1, nullptr, 1);
    // FFN2 split-K=2: psum[z] = ff1[:, z*2048:(z+1)*2048] @ W2[z*2048:(z+1)*2048, :]
    h16_gemm<<<dim3(E_/BN, NROWS/BM, 2), 128, GSMEM>>>(
        ff116, w216, psum, nullptr, NROWS, E_, FF/2, FF, nullptr, nullptr, 0);
    // out = x1 + psum0 + psum1 + b2
    add4_kernel<<<NROWS * E_ / 4 / 256, 256>>>(x1, psum, psum + (size_t)NROWS * E_, b2, out);
}

// round 15
// speedup vs baseline: 1.0637x; 1.0637x over previous
#include <cuda_runtime.h>
#include <cuda_fp16.h>
#include <math.h>
#include <stdint.h>
#include <mma.h>

using namespace nvcuda;

#define B_  2
#define T_  2048
#define E_  1024
#define H_  16
#define HS_ 64
#define NROWS (B_*T_)   // 4096 rows
#define FF  (4*E_)      // 4096

// ---------------- scratch ----------------------------------------------------
__device__ __half g_h16  [NROWS * E_];      // LN1 output (fp16)
__device__ __half g_wqkv16[E_ * 3 * E_];    // repacked QKV weights [E,3E] fp16
__device__ __half g_wp16 [E_ * E_];
__device__ __half g_w116 [E_ * FF];
__device__ __half g_w216 [FF * E_];
__device__ __half g_qkv16[NROWS * 3 * E_];  // Q|K|V fp16
__device__ __half g_attn16[NROWS * E_];     // attention out fp16
__device__ float  g_x1   [NROWS * E_];      // residual 1 (fp32)
__device__ __half g_h2_16[NROWS * E_];      // LN2 output fp16
__device__ __half g_ff116[NROWS * FF];      // FFN hidden fp16

__device__ __forceinline__ void cp_async16(uint32_t dst, const void* src) {
    asm volatile("cp.async.cg.shared.global [%0], [%1], 16;" :: "r"(dst), "l"(src));
}
__device__ __forceinline__ uint32_t smem_u32(const void* p) {
    uint32_t a;
    asm("{ .reg .u64 t; cvta.to.shared.u64 t, %1; cvt.u32.u64 %0, t; }" : "=r"(a) : "l"(p));
    return a;
}
// D += A*B, m16n8k16 fp16 inputs, fp32 accum
__device__ __forceinline__ void mma16(float* c, const uint32_t* a, uint32_t b0, uint32_t b1) {
    asm volatile("mma.sync.aligned.m16n8k16.row.col.f32.f16.f16.f32 "
        "{%0,%1,%2,%3}, {%4,%5,%6,%7}, {%8,%9}, {%0,%1,%2,%3};"
        : "+f"(c[0]), "+f"(c[1]), "+f"(c[2]), "+f"(c[3])
        : "r"(a[0]), "r"(a[1]), "r"(a[2]), "r"(a[3]), "r"(b0), "r"(b1));
}
__device__ __forceinline__ void ldsm4(uint32_t* r, uint32_t a) {
    asm volatile("ldmatrix.sync.aligned.m8n8.x4.shared.b16 {%0,%1,%2,%3}, [%4];"
        : "=r"(r[0]), "=r"(r[1]), "=r"(r[2]), "=r"(r[3]) : "r"(a));
}
__device__ __forceinline__ void ldsm4t(uint32_t* r, uint32_t a) {
    asm volatile("ldmatrix.sync.aligned.m8n8.x4.trans.shared.b16 {%0,%1,%2,%3}, [%4];"
        : "=r"(r[0]), "=r"(r[1]), "=r"(r[2]), "=r"(r[3]) : "r"(a));
}

// ---------------- LayerNorm (fp32 in -> fp16 out) ----------------------------
__global__ __launch_bounds__(256) void ln_kernel(const float* __restrict__ x,
                                                 const float* __restrict__ g,
                                                 const float* __restrict__ b,
                                                 __half* __restrict__ out)
{
    int row = blockIdx.x;
    int tid = threadIdx.x;
    const float4* xr = reinterpret_cast<const float4*>(x + (size_t)row * E_);
    float4 v = xr[tid];
    float s  = v.x + v.y + v.z + v.w;
    float sq = v.x*v.x + v.y*v.y + v.z*v.z + v.w*v.w;

    __shared__ float sh[16];
    __shared__ float s_mu, s_rs;
    #pragma unroll
    for (int o = 16; o > 0; o >>= 1) {
        s  += __shfl_down_sync(0xffffffffu, s,  o);
        sq += __shfl_down_sync(0xffffffffu, sq, o);
    }
    int lane = tid & 31, wid = tid >> 5;
    if (lane == 0) { sh[wid] = s; sh[8 + wid] = sq; }
    __syncthreads();
    if (tid == 0) {
        float ts = 0.f, tq = 0.f;
        #pragma unroll
        for (int w = 0; w < 8; w++) { ts += sh[w]; tq += sh[8 + w]; }
        float mu  = ts * (1.0f / E_);
        float var = tq * (1.0f / E_) - mu * mu;
        s_mu = mu;
        s_rs = rsqrtf(var + 1e-5f);
    }
    __syncthreads();
    float mu = s_mu, rs = s_rs;
    float4 gg = reinterpret_cast<const float4*>(g)[tid];
    float4 bb = reinterpret_cast<const float4*>(b)[tid];
    __half2 h0 = __floats2half2_rn((v.x - mu) * rs * gg.x + bb.x,
                                   (v.y - mu) * rs * gg.y + bb.y);
    __half2 h1 = __floats2half2_rn((v.z - mu) * rs * gg.z + bb.z,
                                   (v.w - mu) * rs * gg.w + bb.w);
    __half2* op = reinterpret_cast<__half2*>(out + (size_t)row * E_ + tid * 4);
    op[0] = h0; op[1] = h1;
}

// ---------------- fused fp32 -> fp16 convert for 3 weights -------------------
__device__ __forceinline__ void cvt8(const float* ip, __half* op) {
    const float4* p = reinterpret_cast<const float4*>(ip);
    float4 a = p[0], b = p[1];
    __half2 h[4] = { __floats2half2_rn(a.x, a.y), __floats2half2_rn(a.z, a.w),
                     __floats2half2_rn(b.x, b.y), __floats2half2_rn(b.z, b.w) };
    *reinterpret_cast<float4*>(op) = *reinterpret_cast<float4*>(h);
}
__global__ void f2h3_kernel(const float* __restrict__ a, __half* __restrict__ oa,
                            const float* __restrict__ b, __half* __restrict__ ob,
                            const float* __restrict__ c, __half* __restrict__ oc,
                            int na8, int nb8, int nc8)
{
    int i = blockIdx.x * blockDim.x + threadIdx.x;
    if (i < na8)                 { cvt8(a + 8 * (size_t)i, oa + 8 * (size_t)i); return; }
    i -= na8;
    if (i < nb8)                 { cvt8(b + 8 * (size_t)i, ob + 8 * (size_t)i); return; }
    i -= nb8;
    if (i < nc8)                 { cvt8(c + 8 * (size_t)i, oc + 8 * (size_t)i); }
}

// ---------------- Repack Wq/Wk/Wv [H,E,HS] -> [E, 3E] fp16 (4/thread) --------
__global__ void repack_kernel(const float* __restrict__ Wq,
                              const float* __restrict__ Wk,
                              const float* __restrict__ Wv,
                              __half* __restrict__ Wqkv)
{
    int i = blockIdx.x * blockDim.x + threadIdx.x;   // over H*E*HS/4
    if (i >= H_ * E_ * HS_ / 4) return;
    int h = i / (E_ * HS_ / 4);
    int r = i % (E_ * HS_ / 4);
    int e = r / (HS_ / 4);
    int d4 = (r % (HS_ / 4)) * 4;
    int col = h * HS_ + d4;
    size_t base = (size_t)e * (3 * E_);
    size_t src = (size_t)i * 4;
    float4 q = *reinterpret_cast<const float4*>(Wq + src);
    float4 k = *reinterpret_cast<const float4*>(Wk + src);
    float4 v = *reinterpret_cast<const float4*>(Wv + src);
    __half2 qh[2] = { __floats2half2_rn(q.x, q.y), __floats2half2_rn(q.z, q.w) };
    __half2 kh[2] = { __floats2half2_rn(k.x, k.y), __floats2half2_rn(k.z, k.w) };
    __half2 vh[2] = { __floats2half2_rn(v.x, v.y), __floats2half2_rn(v.z, v.w) };
    *reinterpret_cast<float2*>(Wqkv + base + col)           = *reinterpret_cast<float2*>(qh);
    *reinterpret_cast<float2*>(Wqkv + base + E_ + col)      = *reinterpret_cast<float2*>(kh);
    *reinterpret_cast<float2*>(Wqkv + base + 2 * E_ + col)  = *reinterpret_cast<float2*>(vh);
}

// ---------------- fp16 WMMA GEMM (m16n16k16, fp32 accum, BK=64) --------------
// EXACT 448.6us build: 128 threads / 4 warps, warp tile 64x64, 3-stage cp.async,
// two barriers per chunk, smem-staged epilogue.
#define BM   128
#define BN   128
#define BKC  64
#define ASTH 72
#define BSTH 136
#define STAGE_H (BM*ASTH + BKC*BSTH)
#define NSTG 3
#define CST  132
#define GSMEM (NSTG * STAGE_H * 2)

__global__ __launch_bounds__(128, 2) void h16_gemm(
    const __half* __restrict__ A, const __half* __restrict__ Bm,
    float* __restrict__ C, __half* __restrict__ Ch, int M, int N, int K,
    const float* __restrict__ bias, const float* __restrict__ res, int relu)
{
    extern __shared__ float sm[];
    __half* smh = reinterpret_cast<__half*>(sm);
    uint32_t smb = smem_u32(sm);

    int tid  = threadIdx.x;
    int wid  = tid >> 5;
    int wm   = wid & 1;
    int wn   = wid >> 1;
    int m0   = blockIdx.y * BM;
    int n0   = blockIdx.x * BN;
    int NC   = K / BKC;

    wmma::fragment<wmma::accumulator, 16, 16, 16, float> acc[4][4];
    #pragma unroll
    for (int i = 0; i < 4; i++)
        #pragma unroll
        for (int j = 0; j < 4; j++)
            wmma::fill_fragment(acc[i][j], 0.0f);

    auto issue = [&](int c) {
        int buf = c % NSTG;
        uint32_t stA = smb + (uint32_t)(buf * STAGE_H) * 2u;
        uint32_t stB = stA + (uint32_t)(BM * ASTH) * 2u;
        int k0 = c * BKC;
        #pragma unroll
        for (int t = 0; t < 8; t++) {
            int idx = tid + t * 128;
            int r  = idx >> 3;
            int kk = (idx & 7) * 8;
            cp_async16(stA + (uint32_t)(r * ASTH + kk) * 2u,
                       A + (size_t)(m0 + r) * K + k0 + kk);
        }
        #pragma unroll
        for (int t = 0; t < 8; t++) {
            int idx = tid + t * 128;
            int r  = idx >> 4;
            int nn = (idx & 15) * 8;
            cp_async16(stB + (uint32_t)(r * BSTH + nn) * 2u,
                       Bm + (size_t)(k0 + r) * N + n0 + nn);
        }
        asm volatile("cp.async.commit_group;" ::: "memory");
    };

    issue(0);
    if (NC > 1) issue(1);

    for (int c = 0; c < NC; c++) {
        if (c + 2 < NC) {
            issue(c + 2);
            asm volatile("cp.async.wait_group 2;" ::: "memory");
        } else if (c + 1 < NC) {
            asm volatile("cp.async.wait_group 1;" ::: "memory");
        } else {
            asm volatile("cp.async.wait_group 0;" ::: "memory");
        }
        __syncthreads();

        const __half* sA = smh + (c % NSTG) * STAGE_H;
        const __half* sB = sA + BM * ASTH;

        #pragma unroll
        for (int kk = 0; kk < 4; kk++) {
            wmma::fragment<wmma::matrix_a, 16, 16, 16, __half, wmma::row_major> af[4];
            wmma::fragment<wmma::matrix_b, 16, 16, 16, __half, wmma::row_major> bf[4];
            #pragma unroll
            for (int i = 0; i < 4; i++)
                wmma::load_matrix_sync(af[i], sA + (wm * 64 + i * 16) * ASTH + kk * 16, ASTH);
            #pragma unroll
            for (int j = 0; j < 4; j++)
                wmma::load_matrix_sync(bf[j], sB + (kk * 16) * BSTH + wn * 64 + j * 16, BSTH);
            #pragma unroll
            for (int i = 0; i < 4; i++)
                #pragma unroll
                for (int j = 0; j < 4; j++)
                    wmma::mma_sync(acc[i][j], af[i], bf[j], acc[i][j]);
        }
        __syncthreads();
    }

    float* Cs = sm;
    #pragma unroll
    for (int i = 0; i < 4; i++)
        #pragma unroll
        for (int j = 0; j < 4; j++)
            wmma::store_matrix_sync(Cs + (wm * 64 + i * 16) * CST + wn * 64 + j * 16,
                                    acc[i][j], CST, wmma::mem_row_major);
    __syncthreads();

    for (int idx = tid; idx < BM * BN / 4; idx += 128) {
        int r  = idx >> 5;
        int c4 = idx & 31;
        float4 v = *reinterpret_cast<const float4*>(Cs + r * CST + c4 * 4);
        int col = n0 + c4 * 4;
        size_t row = (size_t)(m0 + r);
        if (bias) {
            float4 bb = *reinterpret_cast<const float4*>(bias + col);
            v.x += bb.x; v.y += bb.y; v.z += bb.z; v.w += bb.w;
        }
        if (relu) {
            v.x = fmaxf(v.x, 0.f); v.y = fmaxf(v.y, 0.f);
            v.z = fmaxf(v.z, 0.f); v.w = fmaxf(v.w, 0.f);
        }
        if (res) {
            float4 rr = *reinterpret_cast<const float4*>(res + row * N + col);
            v.x += rr.x; v.y += rr.y; v.z += rr.z; v.w += rr.w;
        }
        if (Ch) {
            __half2* hp = reinterpret_cast<__half2*>(Ch + row * N + col);
            hp[0] = __floats2half2_rn(v.x, v.y);
            hp[1] = __floats2half2_rn(v.z, v.w);
        } else {
            *reinterpret_cast<float4*>(C + row * N + col) = v;
        }
    }
}

// ---------------- fp16 tensor-core causal flash attention --------------------
// 256 threads = 8 warps; q-block 128 rows (warp w owns rows [16w,16w+16)).
// K/V 64x64 tiles amortized over 2x q-rows; register P; ldmatrix K/V.
#define APH 72

__global__ __launch_bounds__(256, 2) void attn_kernel(const __half* __restrict__ qkv,
                                                      __half* __restrict__ out)
{
    __shared__ __half asm16[4 * 64 * APH];      // K0,K1,V0,V1 = 36864 B
    uint32_t smu = smem_u32(asm16);

    int tid = threadIdx.x, w = tid >> 5, lane = tid & 31;
    int gid = lane >> 2, tig = lane & 3;
    int g8  = lane >> 3, i8 = lane & 7;
    int qt = (T_ / 128 - 1) - blockIdx.x;       // heavy blocks first; 128-row q block
    int bh = blockIdx.y, b = bh >> 4, h = bh & 15;

    int rowK = ((g8 >> 1) << 3) + i8;
    int colK = (g8 & 1) << 3;
    int rowV = ((g8 & 1) << 3) + i8;
    int colV = (g8 >> 1) << 3;

    // ---- Q fragments (fp16 packed, scaled) ----
    uint32_t qa[4][4];
    {
        const __half2 sc2 = __floats2half2_rn(0.125f, 0.125f);
        #pragma unroll
        for (int ks = 0; ks < 4; ks++)
            #pragma unroll
            for (int r = 0; r < 4; r++) {
                int row = qt * 128 + w * 16 + gid + (r & 1) * 8;
                int col = ks * 16 + 2 * tig + ((r >> 1) * 8);
                __half2 v = *reinterpret_cast<const __half2*>(
                    qkv + (size_t)(b * T_ + row) * (3 * E_) + h * HS_ + col);
                v = __hmul2(v, sc2);
                qa[ks][r] = *reinterpret_cast<uint32_t*>(&v);
            }
    }

    float oa[8][4];
    #pragma unroll
    for (int nt = 0; nt < 8; nt++)
        #pragma unroll
        for (int r = 0; r < 4; r++) oa[nt][r] = 0.f;
    float m0 = -1e30f, m1 = -1e30f, l0 = 0.f, l1 = 0.f;

    // ---- K/V tile loader (double buffered; 256 threads, 2+2 cp each) ----
    auto loadKV = [&](int kt, int bu) {
        const __half* kb = qkv + (size_t)(b * T_ + kt * 64) * (3 * E_) + E_ + h * HS_;
        const __half* vb = kb + E_;
        uint32_t kbase = smu + (uint32_t)(bu * 64 * APH) * 2u;
        uint32_t vbase = smu + (uint32_t)((2 + bu) * 64 * APH) * 2u;
        #pragma unroll
        for (int t = 0; t < 2; t++) {
            int i = tid + t * 256;
            int r = i >> 3, c = (i & 7) * 8;
            cp_async16(kbase + (uint32_t)(r * APH + c) * 2u, kb + (size_t)r * (3 * E_) + c);
            cp_async16(vbase + (uint32_t)(r * APH + c) * 2u, vb + (size_t)r * (3 * E_) + c);
        }
        asm volatile("cp.async.commit_group;" ::: "memory");
    };

    int last = 2 * qt + 1;                      // tiles kt = 0..last (64-key tiles)
    loadKV(0, 0);

    for (int kt = 0; kt <= last; kt++) {
        int bu = kt & 1;
        if (kt < last) {
            loadKV(kt + 1, bu ^ 1);
            asm volatile("cp.async.wait_group 1;" ::: "memory");
        } else {
            asm volatile("cp.async.wait_group 0;" ::: "memory");
        }
        __syncthreads();

        // warps 0-3 (q rows < 64 in-block) have no keys in the last tile
        bool active = !(kt == last && w < 4);
        if (active) {
            uint32_t kbase = smu + (uint32_t)(bu * 64 * APH) * 2u;
            uint32_t vbase = smu + (uint32_t)((2 + bu) * 64 * APH) * 2u;

            float sa[8][4];
            #pragma unroll
            for (int nt = 0; nt < 8; nt++)
                #pragma unroll
                for (int r = 0; r < 4; r++) sa[nt][r] = 0.f;

            #pragma unroll
            for (int ks = 0; ks < 4; ks++) {
                #pragma unroll
                for (int ntp = 0; ntp < 4; ntp++) {
                    uint32_t kf[4];
                    ldsm4(kf, kbase + (uint32_t)((ntp * 16 + rowK) * APH + ks * 16 + colK) * 2u);
                    mma16(sa[2 * ntp],     qa[ks], kf[0], kf[1]);
                    mma16(sa[2 * ntp + 1], qa[ks], kf[2], kf[3]);
                }
            }

            // causal mask: only diagonal-zone tiles (kt >= 2*qt)
            if (kt >= 2 * qt) {
                int r0 = w * 16 + gid, r1 = r0 + 8;        // local q row in 128-block
                int koff = (kt - 2 * qt) * 64;             // local key offset
                #pragma unroll
                for (int nt = 0; nt < 8; nt++) {
                    int c0 = koff + nt * 8 + 2 * tig, c1 = c0 + 1;
                    if (c0 > r0) sa[nt][0] = -1e30f;
                    if (c1 > r0) sa[nt][1] = -1e30f;
                    if (c0 > r1) sa[nt][2] = -1e30f;
                    if (c1 > r1) sa[nt][3] = -1e30f;
                }
            }

            float mt0 = -1e30f, mt1 = -1e30f;
            #pragma unroll
            for (int nt = 0; nt < 8; nt++) {
                mt0 = fmaxf(mt0, fmaxf(sa[nt][0], sa[nt][1]));
                mt1 = fmaxf(mt1, fmaxf(sa[nt][2], sa[nt][3]));
            }
            mt0 = fmaxf(mt0, __shfl_xor_sync(0xffffffffu, mt0, 1));
            mt0 = fmaxf(mt0, __shfl_xor_sync(0xffffffffu, mt0, 2));
            mt1 = fmaxf(mt1, __shfl_xor_sync(0xffffffffu, mt1, 1));
            mt1 = fmaxf(mt1, __shfl_xor_sync(0xffffffffu, mt1, 2));

            float mn0 = fmaxf(m0, mt0), mn1 = fmaxf(m1, mt1);
            float cr0 = __expf(m0 - mn0), cr1 = __expf(m1 - mn1);
            m0 = mn0; m1 = mn1;

            float s0 = 0.f, s1 = 0.f;
            uint32_t ph0[8], ph1[8];
            #pragma unroll
            for (int nt = 0; nt < 8; nt++) {
                float e0 = __expf(sa[nt][0] - mn0), e1 = __expf(sa[nt][1] - mn0);
                float e2 = __expf(sa[nt][2] - mn1), e3 = __expf(sa[nt][3] - mn1);
                s0 += e0 + e1;  s1 += e2 + e3;
                __half2 hp0 = __floats2half2_rn(e0, e1);
                __half2 hp1 = __floats2half2_rn(e2, e3);
                ph0[nt] = *reinterpret_cast<uint32_t*>(&hp0);
                ph1[nt] = *reinterpret_cast<uint32_t*>(&hp1);
            }
            s0 += __shfl_xor_sync(0xffffffffu, s0, 1);
            s0 += __shfl_xor_sync(0xffffffffu, s0, 2);
            s1 += __shfl_xor_sync(0xffffffffu, s1, 1);
            s1 += __shfl_xor_sync(0xffffffffu, s1, 2);
            l0 = l0 * cr0 + s0;
            l1 = l1 * cr1 + s1;

            #pragma unroll
            for (int nt = 0; nt < 8; nt++) {
                oa[nt][0] *= cr0; oa[nt][1] *= cr0;
                oa[nt][2] *= cr1; oa[nt][3] *= cr1;
            }

            #pragma unroll
            for (int ks = 0; ks < 4; ks++) {
                uint32_t pa[4] = { ph0[2 * ks], ph1[2 * ks], ph0[2 * ks + 1], ph1[2 * ks + 1] };
                #pragma unroll
                for (int ntp = 0; ntp < 4; ntp++) {
                    uint32_t vf[4];
                    ldsm4t(vf, vbase + (uint32_t)((ks * 16 + rowV) * APH + ntp * 16 + colV) * 2u);
                    mma16(oa[2 * ntp],     pa, vf[0], vf[1]);
                    mma16(oa[2 * ntp + 1], pa, vf[2], vf[3]);
                }
            }
        }
        __syncthreads();
    }

    // ---- finalize ----
    float i0 = 1.f / l0, i1 = 1.f / l1;
    int r0 = qt * 128 + w * 16 + gid;
    #pragma unroll
    for (int nt = 0; nt < 8; nt++) {
        int col = h * HS_ + nt * 8 + 2 * tig;
        __half2* p0 = reinterpret_cast<__half2*>(out + (size_t)(b * T_ + r0) * E_ + col);
        __half2* p1 = reinterpret_cast<__half2*>(out + (size_t)(b * T_ + r0 + 8) * E_ + col);
        *p0 = __floats2half2_rn(oa[nt][0] * i0, oa[nt][1] * i0);
        *p1 = __floats2half2_rn(oa[nt][2] * i1, oa[nt][3] * i1);
    }
}

// ---------------- host -------------------------------------------------------
extern "C" void kernel_launch(void* const* d_in, const int* in_sizes, int n_in,
                              void* d_out, int out_size)
{
    const float* x   = (const float*)d_in[0];
    const float* Wq  = (const float*)d_in[1];
    const float* Wk  = (const float*)d_in[2];
    const float* Wv  = (const float*)d_in[3];
    const float* Wp  = (const float*)d_in[4];
    const float* bp  = (const float*)d_in[5];
    const float* W1  = (const float*)d_in[6];
    const float* b1  = (const float*)d_in[7];
    const float* W2  = (const float*)d_in[8];
    const float* b2  = (const float*)d_in[9];
    const float* g1  = (const float*)d_in[10];
    const float* be1 = (const float*)d_in[11];
    const float* g2  = (const float*)d_in[12];
    const float* be2 = (const float*)d_in[13];
    float* out = (float*)d_out;

    __half *h16, *wqkv16, *wp16, *w116, *w216, *qkv16, *attn16, *h2_16, *ff116;
    float *x1;
    cudaGetSymbolAddress((void**)&h16,    g_h16);
    cudaGetSymbolAddress((void**)&wqkv16, g_wqkv16);
    cudaGetSymbolAddress((void**)&wp16,   g_wp16);
    cudaGetSymbolAddress((void**)&w116,   g_w116);
    cudaGetSymbolAddress((void**)&w216,   g_w216);
    cudaGetSymbolAddress((void**)&qkv16,  g_qkv16);
    cudaGetSymbolAddress((void**)&attn16, g_attn16);
    cudaGetSymbolAddress((void**)&x1,     g_x1);
    cudaGetSymbolAddress((void**)&h2_16,  g_h2_16);
    cudaGetSymbolAddress((void**)&ff116,  g_ff116);

    cudaFuncSetAttribute(h16_gemm, cudaFuncAttributeMaxDynamicSharedMemorySize, GSMEM);

    // prep: LN1, repack, fused weight converts
    ln_kernel<<<NROWS, 256>>>(x, g1, be1, h16);
    repack_kernel<<<(H_ * E_ * HS_ / 4 + 255) / 256, 256>>>(Wq, Wk, Wv, wqkv16);
    {
        int na8 = E_ * E_ / 8, nb8 = E_ * FF / 8, nc8 = FF * E_ / 8;
        f2h3_kernel<<<(na8 + nb8 + nc8 + 255) / 256, 256>>>(
            Wp, wp16, W1, w116, W2, w216, na8, nb8, nc8);
    }

    // QKV = h @ Wqkv -> fp16
    h16_gemm<<<dim3(3*E_/BN, NROWS/BM), 128, GSMEM>>>(
        h16, wqkv16, nullptr, qkv16, NROWS, 3*E_, E_, nullptr, nullptr, 0);
    // attention (fp16 tensor cores, 128-row q blocks) -> fp16
    attn_kernel<<<dim3(T_/128, B_*H_), 256>>>(qkv16, attn16);
    // x1 = x + attn @ Wp + bp  (fp32 out)
    h16_gemm<<<dim3(E_/BN, NROWS/BM), 128, GSMEM>>>(
        attn16, wp16, x1, nullptr, NROWS, E_, E_, bp, x, 0);
    // h2 = LN2(x1) -> fp16
    ln_kernel<<<NROWS, 256>>>(x1, g2, be2, h2_16);
    // ff1 = relu(h2 @ W1 + b1) -> fp16
    h16_gemm<<<dim3(FF/BN, NROWS/BM), 128, GSMEM>>>(
        h2_16, w116, nullptr, ff116, NROWS, FF, E_, b1, nullptr, 1);
    // out = x1 + ff1 @ W2 + b2  (fp32 out, K = 4096)
    h16_gemm<<<dim3(E_/BN, NROWS/BM), 128, GSMEM>>>(
        ff116, w216, out, nullptr, NROWS, E_, FF, b2, x1, 0);
}

// round 16
// speedup vs baseline: 1.0881x; 1.0229x over previous
#include <cuda_runtime.h>
#include <cuda_fp16.h>
#include <math.h>
#include <stdint.h>
#include <mma.h>

using namespace nvcuda;

#define B_  2
#define T_  2048
#define E_  1024
#define H_  16
#define HS_ 64
#define NROWS (B_*T_)   // 4096 rows
#define FF  (4*E_)      // 4096

// ---------------- scratch ----------------------------------------------------
__device__ __half g_h16  [NROWS * E_];      // LN1 output (fp16)
__device__ __half g_wqkv16[E_ * 3 * E_];    // repacked QKV weights [E,3E] fp16
__device__ __half g_wp16 [E_ * E_];
__device__ __half g_w116 [E_ * FF];
__device__ __half g_w216 [FF * E_];
__device__ __half g_qkv16[NROWS * 3 * E_];  // Q|K|V fp16
__device__ __half g_attn16[NROWS * E_];     // attention out fp16
__device__ float  g_x1   [NROWS * E_];      // residual 1 (fp32)
__device__ __half g_h2_16[NROWS * E_];      // LN2 output fp16
__device__ __half g_ff116[NROWS * FF];      // FFN hidden fp16

__device__ __forceinline__ void cp_async16(uint32_t dst, const void* src) {
    asm volatile("cp.async.cg.shared.global [%0], [%1], 16;" :: "r"(dst), "l"(src));
}
__device__ __forceinline__ uint32_t smem_u32(const void* p) {
    uint32_t a;
    asm("{ .reg .u64 t; cvta.to.shared.u64 t, %1; cvt.u32.u64 %0, t; }" : "=r"(a) : "l"(p));
    return a;
}
// D += A*B, m16n8k16 fp16 inputs, fp32 accum
__device__ __forceinline__ void mma16(float* c, const uint32_t* a, uint32_t b0, uint32_t b1) {
    asm volatile("mma.sync.aligned.m16n8k16.row.col.f32.f16.f16.f32 "
        "{%0,%1,%2,%3}, {%4,%5,%6,%7}, {%8,%9}, {%0,%1,%2,%3};"
        : "+f"(c[0]), "+f"(c[1]), "+f"(c[2]), "+f"(c[3])
        : "r"(a[0]), "r"(a[1]), "r"(a[2]), "r"(a[3]), "r"(b0), "r"(b1));
}
__device__ __forceinline__ void ldsm4(uint32_t* r, uint32_t a) {
    asm volatile("ldmatrix.sync.aligned.m8n8.x4.shared.b16 {%0,%1,%2,%3}, [%4];"
        : "=r"(r[0]), "=r"(r[1]), "=r"(r[2]), "=r"(r[3]) : "r"(a));
}
__device__ __forceinline__ void ldsm4t(uint32_t* r, uint32_t a) {
    asm volatile("ldmatrix.sync.aligned.m8n8.x4.trans.shared.b16 {%0,%1,%2,%3}, [%4];"
        : "=r"(r[0]), "=r"(r[1]), "=r"(r[2]), "=r"(r[3]) : "r"(a));
}

// ---------------- LayerNorm (fp32 in -> fp16 out) ----------------------------
__global__ __launch_bounds__(256) void ln_kernel(const float* __restrict__ x,
                                                 const float* __restrict__ g,
                                                 const float* __restrict__ b,
                                                 __half* __restrict__ out)
{
    int row = blockIdx.x;
    int tid = threadIdx.x;
    const float4* xr = reinterpret_cast<const float4*>(x + (size_t)row * E_);
    float4 v = xr[tid];
    float s  = v.x + v.y + v.z + v.w;
    float sq = v.x*v.x + v.y*v.y + v.z*v.z + v.w*v.w;

    __shared__ float sh[16];
    __shared__ float s_mu, s_rs;
    #pragma unroll
    for (int o = 16; o > 0; o >>= 1) {
        s  += __shfl_down_sync(0xffffffffu, s,  o);
        sq += __shfl_down_sync(0xffffffffu, sq, o);
    }
    int lane = tid & 31, wid = tid >> 5;
    if (lane == 0) { sh[wid] = s; sh[8 + wid] = sq; }
    __syncthreads();
    if (tid == 0) {
        float ts = 0.f, tq = 0.f;
        #pragma unroll
        for (int w = 0; w < 8; w++) { ts += sh[w]; tq += sh[8 + w]; }
        float mu  = ts * (1.0f / E_);
        float var = tq * (1.0f / E_) - mu * mu;
        s_mu = mu;
        s_rs = rsqrtf(var + 1e-5f);
    }
    __syncthreads();
    float mu = s_mu, rs = s_rs;
    float4 gg = reinterpret_cast<const float4*>(g)[tid];
    float4 bb = reinterpret_cast<const float4*>(b)[tid];
    __half2 h0 = __floats2half2_rn((v.x - mu) * rs * gg.x + bb.x,
                                   (v.y - mu) * rs * gg.y + bb.y);
    __half2 h1 = __floats2half2_rn((v.z - mu) * rs * gg.z + bb.z,
                                   (v.w - mu) * rs * gg.w + bb.w);
    __half2* op = reinterpret_cast<__half2*>(out + (size_t)row * E_ + tid * 4);
    op[0] = h0; op[1] = h1;
}

// ---------------- fused prep: repack QKV + f2h of Wp/W1/W2 -------------------
__device__ __forceinline__ void cvt8(const float* ip, __half* op) {
    const float4* p = reinterpret_cast<const float4*>(ip);
    float4 a = p[0], b = p[1];
    __half2 h[4] = { __floats2half2_rn(a.x, a.y), __floats2half2_rn(a.z, a.w),
                     __floats2half2_rn(b.x, b.y), __floats2half2_rn(b.z, b.w) };
    *reinterpret_cast<float4*>(op) = *reinterpret_cast<float4*>(h);
}
#define RP4  (H_ * E_ * HS_ / 4)      // repack work items (4 elems each)
__global__ void prep_kernel(const float* __restrict__ Wq, const float* __restrict__ Wk,
                            const float* __restrict__ Wv, __half* __restrict__ Wqkv,
                            const float* __restrict__ Wp, __half* __restrict__ wp16,
                            const float* __restrict__ W1, __half* __restrict__ w116,
                            const float* __restrict__ W2, __half* __restrict__ w216)
{
    int i = blockIdx.x * blockDim.x + threadIdx.x;
    if (i < RP4) {
        int h = i / (E_ * HS_ / 4);
        int r = i % (E_ * HS_ / 4);
        int e = r / (HS_ / 4);
        int d4 = (r % (HS_ / 4)) * 4;
        int col = h * HS_ + d4;
        size_t base = (size_t)e * (3 * E_);
        size_t src = (size_t)i * 4;
        float4 q = *reinterpret_cast<const float4*>(Wq + src);
        float4 k = *reinterpret_cast<const float4*>(Wk + src);
        float4 v = *reinterpret_cast<const float4*>(Wv + src);
        __half2 qh[2] = { __floats2half2_rn(q.x, q.y), __floats2half2_rn(q.z, q.w) };
        __half2 kh[2] = { __floats2half2_rn(k.x, k.y), __floats2half2_rn(k.z, k.w) };
        __half2 vh[2] = { __floats2half2_rn(v.x, v.y), __floats2half2_rn(v.z, v.w) };
        *reinterpret_cast<float2*>(Wqkv + base + col)           = *reinterpret_cast<float2*>(qh);
        *reinterpret_cast<float2*>(Wqkv + base + E_ + col)      = *reinterpret_cast<float2*>(kh);
        *reinterpret_cast<float2*>(Wqkv + base + 2 * E_ + col)  = *reinterpret_cast<float2*>(vh);
        return;
    }
    int j = i - RP4;                              // 8-elem convert items
    int na8 = E_ * E_ / 8, nb8 = E_ * FF / 8, nc8 = FF * E_ / 8;
    if (j < na8)      { cvt8(Wp + 8 * (size_t)j, wp16 + 8 * (size_t)j); return; }
    j -= na8;
    if (j < nb8)      { cvt8(W1 + 8 * (size_t)j, w116 + 8 * (size_t)j); return; }
    j -= nb8;
    if (j < nc8)      { cvt8(W2 + 8 * (size_t)j, w216 + 8 * (size_t)j); }
}

// ---------------- fp16 WMMA GEMM (m16n16k16, fp32 accum, BK=64) --------------
// best-known config: 128 threads / 4 warps, warp tile 64x64, 3-stage cp.async.
#define BM   128
#define BN   128
#define BKC  64
#define ASTH 72
#define BSTH 136
#define STAGE_H (BM*ASTH + BKC*BSTH)
#define NSTG 3
#define CST  132
#define GSMEM (NSTG * STAGE_H * 2)

__global__ __launch_bounds__(128, 2) void h16_gemm(
    const __half* __restrict__ A, const __half* __restrict__ Bm,
    float* __restrict__ C, __half* __restrict__ Ch, int M, int N, int K,
    const float* __restrict__ bias, const float* __restrict__ res, int relu)
{
    extern __shared__ float sm[];
    __half* smh = reinterpret_cast<__half*>(sm);
    uint32_t smb = smem_u32(sm);

    int tid  = threadIdx.x;
    int wid  = tid >> 5;
    int wm   = wid & 1;
    int wn   = wid >> 1;
    int m0   = blockIdx.y * BM;
    int n0   = blockIdx.x * BN;
    int NC   = K / BKC;

    wmma::fragment<wmma::accumulator, 16, 16, 16, float> acc[4][4];
    #pragma unroll
    for (int i = 0; i < 4; i++)
        #pragma unroll
        for (int j = 0; j < 4; j++)
            wmma::fill_fragment(acc[i][j], 0.0f);

    auto issue = [&](int c) {
        int buf = c % NSTG;
        uint32_t stA = smb + (uint32_t)(buf * STAGE_H) * 2u;
        uint32_t stB = stA + (uint32_t)(BM * ASTH) * 2u;
        int k0 = c * BKC;
        #pragma unroll
        for (int t = 0; t < 8; t++) {
            int idx = tid + t * 128;
            int r  = idx >> 3;
            int kk = (idx & 7) * 8;
            cp_async16(stA + (uint32_t)(r * ASTH + kk) * 2u,
                       A + (size_t)(m0 + r) * K + k0 + kk);
        }
        #pragma unroll
        for (int t = 0; t < 8; t++) {
            int idx = tid + t * 128;
            int r  = idx >> 4;
            int nn = (idx & 15) * 8;
            cp_async16(stB + (uint32_t)(r * BSTH + nn) * 2u,
                       Bm + (size_t)(k0 + r) * N + n0 + nn);
        }
        asm volatile("cp.async.commit_group;" ::: "memory");
    };

    issue(0);
    if (NC > 1) issue(1);

    for (int c = 0; c < NC; c++) {
        if (c + 2 < NC) {
            issue(c + 2);
            asm volatile("cp.async.wait_group 2;" ::: "memory");
        } else if (c + 1 < NC) {
            asm volatile("cp.async.wait_group 1;" ::: "memory");
        } else {
            asm volatile("cp.async.wait_group 0;" ::: "memory");
        }
        __syncthreads();

        const __half* sA = smh + (c % NSTG) * STAGE_H;
        const __half* sB = sA + BM * ASTH;

        #pragma unroll
        for (int kk = 0; kk < 4; kk++) {
            wmma::fragment<wmma::matrix_a, 16, 16, 16, __half, wmma::row_major> af[4];
            wmma::fragment<wmma::matrix_b, 16, 16, 16, __half, wmma::row_major> bf[4];
            #pragma unroll
            for (int i = 0; i < 4; i++)
                wmma::load_matrix_sync(af[i], sA + (wm * 64 + i * 16) * ASTH + kk * 16, ASTH);
            #pragma unroll
            for (int j = 0; j < 4; j++)
                wmma::load_matrix_sync(bf[j], sB + (kk * 16) * BSTH + wn * 64 + j * 16, BSTH);
            #pragma unroll
            for (int i = 0; i < 4; i++)
                #pragma unroll
                for (int j = 0; j < 4; j++)
                    wmma::mma_sync(acc[i][j], af[i], bf[j], acc[i][j]);
        }
        __syncthreads();
    }

    float* Cs = sm;
    #pragma unroll
    for (int i = 0; i < 4; i++)
        #pragma unroll
        for (int j = 0; j < 4; j++)
            wmma::store_matrix_sync(Cs + (wm * 64 + i * 16) * CST + wn * 64 + j * 16,
                                    acc[i][j], CST, wmma::mem_row_major);
    __syncthreads();

    for (int idx = tid; idx < BM * BN / 4; idx += 128) {
        int r  = idx >> 5;
        int c4 = idx & 31;
        float4 v = *reinterpret_cast<const float4*>(Cs + r * CST + c4 * 4);
        int col = n0 + c4 * 4;
        size_t row = (size_t)(m0 + r);
        if (bias) {
            float4 bb = *reinterpret_cast<const float4*>(bias + col);
            v.x += bb.x; v.y += bb.y; v.z += bb.z; v.w += bb.w;
        }
        if (relu) {
            v.x = fmaxf(v.x, 0.f); v.y = fmaxf(v.y, 0.f);
            v.z = fmaxf(v.z, 0.f); v.w = fmaxf(v.w, 0.f);
        }
        if (res) {
            float4 rr = *reinterpret_cast<const float4*>(res + row * N + col);
            v.x += rr.x; v.y += rr.y; v.z += rr.z; v.w += rr.w;
        }
        if (Ch) {
            __half2* hp = reinterpret_cast<__half2*>(Ch + row * N + col);
            hp[0] = __floats2half2_rn(v.x, v.y);
            hp[1] = __floats2half2_rn(v.z, v.w);
        } else {
            *reinterpret_cast<float4*>(C + row * N + col) = v;
        }
    }
}

// ---------------- fp16 tensor-core causal flash attention --------------------
// 128 threads = 4 warps; q-block 64 rows; register P; ldmatrix K/V; exp2 softmax.
#define APH 72

__global__ __launch_bounds__(128) void attn_kernel(const __half* __restrict__ qkv,
                                                   __half* __restrict__ out)
{
    __shared__ __half asm16[4 * 64 * APH];
    uint32_t smu = smem_u32(asm16);

    int tid = threadIdx.x, w = tid >> 5, lane = tid & 31;
    int gid = lane >> 2, tig = lane & 3;
    int g8  = lane >> 3, i8 = lane & 7;
    int qt = (T_ / 64 - 1) - blockIdx.x;
    int bh = blockIdx.y, b = bh >> 4, h = bh & 15;

    int rowK = ((g8 >> 1) << 3) + i8;
    int colK = (g8 & 1) << 3;
    int rowV = ((g8 & 1) << 3) + i8;
    int colV = (g8 >> 1) << 3;

    // Q scaled by HS^-1/2 * log2(e): softmax computed in base 2 throughout.
    uint32_t qa[4][4];
    {
        const __half2 sc2 = __floats2half2_rn(0.18033688f, 0.18033688f);  // 0.125*log2(e)
        #pragma unroll
        for (int ks = 0; ks < 4; ks++)
            #pragma unroll
            for (int r = 0; r < 4; r++) {
                int row = w * 16 + gid + (r & 1) * 8;
                int col = ks * 16 + 2 * tig + ((r >> 1) * 8);
                __half2 v = *reinterpret_cast<const __half2*>(
                    qkv + (size_t)(b * T_ + qt * 64 + row) * (3 * E_) + h * HS_ + col);
                v = __hmul2(v, sc2);
                qa[ks][r] = *reinterpret_cast<uint32_t*>(&v);
            }
    }

    float oa[8][4];
    #pragma unroll
    for (int nt = 0; nt < 8; nt++)
        #pragma unroll
        for (int r = 0; r < 4; r++) oa[nt][r] = 0.f;
    float m0 = -1e30f, m1 = -1e30f, l0 = 0.f, l1 = 0.f;

    auto loadKV = [&](int kt, int bu) {
        const __half* kb = qkv + (size_t)(b * T_ + kt * 64) * (3 * E_) + E_ + h * HS_;
        const __half* vb = kb + E_;
        uint32_t kbase = smu + (uint32_t)(bu * 64 * APH) * 2u;
        uint32_t vbase = smu + (uint32_t)((2 + bu) * 64 * APH) * 2u;
        #pragma unroll
        for (int t = 0; t < 4; t++) {
            int i = tid + t * 128;
            int r = i >> 3, c = (i & 7) * 8;
            cp_async16(kbase + (uint32_t)(r * APH + c) * 2u, kb + (size_t)r * (3 * E_) + c);
            cp_async16(vbase + (uint32_t)(r * APH + c) * 2u, vb + (size_t)r * (3 * E_) + c);
        }
        asm volatile("cp.async.commit_group;" ::: "memory");
    };

    loadKV(0, 0);

    for (int kt = 0; kt <= qt; kt++) {
        int bu = kt & 1;
        if (kt < qt) {
            loadKV(kt + 1, bu ^ 1);
            asm volatile("cp.async.wait_group 1;" ::: "memory");
        } else {
            asm volatile("cp.async.wait_group 0;" ::: "memory");
        }
        __syncthreads();

        uint32_t kbase = smu + (uint32_t)(bu * 64 * APH) * 2u;
        uint32_t vbase = smu + (uint32_t)((2 + bu) * 64 * APH) * 2u;

        float sa[8][4];
        #pragma unroll
        for (int nt = 0; nt < 8; nt++)
            #pragma unroll
            for (int r = 0; r < 4; r++) sa[nt][r] = 0.f;

        #pragma unroll
        for (int ks = 0; ks < 4; ks++) {
            #pragma unroll
            for (int ntp = 0; ntp < 4; ntp++) {
                uint32_t kf[4];
                ldsm4(kf, kbase + (uint32_t)((ntp * 16 + rowK) * APH + ks * 16 + colK) * 2u);
                mma16(sa[2 * ntp],     qa[ks], kf[0], kf[1]);
                mma16(sa[2 * ntp + 1], qa[ks], kf[2], kf[3]);
            }
        }

        if (kt == qt) {
            int r0 = w * 16 + gid, r1 = r0 + 8;
            #pragma unroll
            for (int nt = 0; nt < 8; nt++) {
                int c0 = nt * 8 + 2 * tig, c1 = c0 + 1;
                if (c0 > r0) sa[nt][0] = -1e30f;
                if (c1 > r0) sa[nt][1] = -1e30f;
                if (c0 > r1) sa[nt][2] = -1e30f;
                if (c1 > r1) sa[nt][3] = -1e30f;
            }
        }

        float mt0 = -1e30f, mt1 = -1e30f;
        #pragma unroll
        for (int nt = 0; nt < 8; nt++) {
            mt0 = fmaxf(mt0, fmaxf(sa[nt][0], sa[nt][1]));
            mt1 = fmaxf(mt1, fmaxf(sa[nt][2], sa[nt][3]));
        }
        mt0 = fmaxf(mt0, __shfl_xor_sync(0xffffffffu, mt0, 1));
        mt0 = fmaxf(mt0, __shfl_xor_sync(0xffffffffu, mt0, 2));
        mt1 = fmaxf(mt1, __shfl_xor_sync(0xffffffffu, mt1, 1));
        mt1 = fmaxf(mt1, __shfl_xor_sync(0xffffffffu, mt1, 2));

        float mn0 = fmaxf(m0, mt0), mn1 = fmaxf(m1, mt1);
        float cr0 = exp2f(m0 - mn0), cr1 = exp2f(m1 - mn1);
        m0 = mn0; m1 = mn1;

        float s0 = 0.f, s1 = 0.f;
        uint32_t ph0[8], ph1[8];
        #pragma unroll
        for (int nt = 0; nt < 8; nt++) {
            float e0 = exp2f(sa[nt][0] - mn0), e1 = exp2f(sa[nt][1] - mn0);
            float e2 = exp2f(sa[nt][2] - mn1), e3 = exp2f(sa[nt][3] - mn1);
            s0 += e0 + e1;  s1 += e2 + e3;
            __half2 hp0 = __floats2half2_rn(e0, e1);
            __half2 hp1 = __floats2half2_rn(e2, e3);
            ph0[nt] = *reinterpret_cast<uint32_t*>(&hp0);
            ph1[nt] = *reinterpret_cast<uint32_t*>(&hp1);
        }
        s0 += __shfl_xor_sync(0xffffffffu, s0, 1);
        s0 += __shfl_xor_sync(0xffffffffu, s0, 2);
        s1 += __shfl_xor_sync(0xffffffffu, s1, 1);
        s1 += __shfl_xor_sync(0xffffffffu, s1, 2);
        l0 = l0 * cr0 + s0;
        l1 = l1 * cr1 + s1;

        #pragma unroll
        for (int nt = 0; nt < 8; nt++) {
            oa[nt][0] *= cr0; oa[nt][1] *= cr0;
            oa[nt][2] *= cr1; oa[nt][3] *= cr1;
        }

        #pragma unroll
        for (int ks = 0; ks < 4; ks++) {
            uint32_t pa[4] = { ph0[2 * ks], ph1[2 * ks], ph0[2 * ks + 1], ph1[2 * ks + 1] };
            #pragma unroll
            for (int ntp = 0; ntp < 4; ntp++) {
                uint32_t vf[4];
                ldsm4t(vf, vbase + (uint32_t)((ks * 16 + rowV) * APH + ntp * 16 + colV) * 2u);
                mma16(oa[2 * ntp],     pa, vf[0], vf[1]);
                mma16(oa[2 * ntp + 1], pa, vf[2], vf[3]);
            }
        }
        __syncthreads();
    }

    float i0 = 1.f / l0, i1 = 1.f / l1;
    int r0 = qt * 64 + w * 16 + gid;
    #pragma unroll
    for (int nt = 0; nt < 8; nt++) {
        int col = h * HS_ + nt * 8 + 2 * tig;
        __half2* p0 = reinterpret_cast<__half2*>(out + (size_t)(b * T_ + r0) * E_ + col);
        __half2* p1 = reinterpret_cast<__half2*>(out + (size_t)(b * T_ + r0 + 8) * E_ + col);
        *p0 = __floats2half2_rn(oa[nt][0] * i0, oa[nt][1] * i0);
        *p1 = __floats2half2_rn(oa[nt][2] * i1, oa[nt][3] * i1);
    }
}

// ---------------- host -------------------------------------------------------
extern "C" void kernel_launch(void* const* d_in, const int* in_sizes, int n_in,
                              void* d_out, int out_size)
{
    const float* x   = (const float*)d_in[0];
    const float* Wq  = (const float*)d_in[1];
    const float* Wk  = (const float*)d_in[2];
    const float* Wv  = (const float*)d_in[3];
    const float* Wp  = (const float*)d_in[4];
    const float* bp  = (const float*)d_in[5];
    const float* W1  = (const float*)d_in[6];
    const float* b1  = (const float*)d_in[7];
    const float* W2  = (const float*)d_in[8];
    const float* b2  = (const float*)d_in[9];
    const float* g1  = (const float*)d_in[10];
    const float* be1 = (const float*)d_in[11];
    const float* g2  = (const float*)d_in[12];
    const float* be2 = (const float*)d_in[13];
    float* out = (float*)d_out;

    __half *h16, *wqkv16, *wp16, *w116, *w216, *qkv16, *attn16, *h2_16, *ff116;
    float *x1;
    cudaGetSymbolAddress((void**)&h16,    g_h16);
    cudaGetSymbolAddress((void**)&wqkv16, g_wqkv16);
    cudaGetSymbolAddress((void**)&wp16,   g_wp16);
    cudaGetSymbolAddress((void**)&w116,   g_w116);
    cudaGetSymbolAddress((void**)&w216,   g_w216);
    cudaGetSymbolAddress((void**)&qkv16,  g_qkv16);
    cudaGetSymbolAddress((void**)&attn16, g_attn16);
    cudaGetSymbolAddress((void**)&x1,     g_x1);
    cudaGetSymbolAddress((void**)&h2_16,  g_h2_16);
    cudaGetSymbolAddress((void**)&ff116,  g_ff116);

    cudaFuncSetAttribute(h16_gemm, cudaFuncAttributeMaxDynamicSharedMemorySize, GSMEM);

    // prep: LN1 + single fused weight-prep kernel
    ln_kernel<<<NROWS, 256>>>(x, g1, be1, h16);
    {
        int total = RP4 + E_ * E_ / 8 + E_ * FF / 8 + FF * E_ / 8;
        prep_kernel<<<(total + 255) / 256, 256>>>(Wq, Wk, Wv, wqkv16,
                                                  Wp, wp16, W1, w116, W2, w216);
    }

    // QKV = h @ Wqkv -> fp16
    h16_gemm<<<dim3(3*E_/BN, NROWS/BM), 128, GSMEM>>>(
        h16, wqkv16, nullptr, qkv16, NROWS, 3*E_, E_, nullptr, nullptr, 0);
    // attention (fp16 tensor cores, register-resident P, exp2 softmax) -> fp16
    attn_kernel<<<dim3(T_/64, B_*H_), 128>>>(qkv16, attn16);
    // x1 = x + attn @ Wp + bp  (fp32 out)
    h16_gemm<<<dim3(E_/BN, NROWS/BM), 128, GSMEM>>>(
        attn16, wp16, x1, nullptr, NROWS, E_, E_, bp, x, 0);
    // h2 = LN2(x1) -> fp16
    ln_kernel<<<NROWS, 256>>>(x1, g2, be2, h2_16);
    // ff1 = relu(h2 @ W1 + b1) -> fp16
    h16_gemm<<<dim3(FF/BN, NROWS/BM), 128, GSMEM>>>(
        h2_16, w116, nullptr, ff116, NROWS, FF, E_, b1, nullptr, 1);
    // out = x1 + ff1 @ W2 + b2  (fp32 out, K = 4096)
    h16_gemm<<<dim3(E_/BN, NROWS/BM), 128, GSMEM>>>(
        ff116, w216, out, nullptr, NROWS, E_, FF, b2, x1, 0);
}

// round 17
// speedup vs baseline: 1.0959x; 1.0072x over previous
#include <cuda_runtime.h>
#include <cuda_fp16.h>
#include <math.h>
#include <stdint.h>
#include <mma.h>

using namespace nvcuda;

#define B_  2
#define T_  2048
#define E_  1024
#define H_  16
#define HS_ 64
#define NROWS (B_*T_)   // 4096 rows
#define FF  (4*E_)      // 4096

// ---------------- scratch ----------------------------------------------------
__device__ __half g_h16  [NROWS * E_];      // LN1 output (fp16)
__device__ __half g_wqkv16[E_ * 3 * E_];    // repacked QKV weights [E,3E] fp16
__device__ __half g_wp16 [E_ * E_];
__device__ __half g_w116 [E_ * FF];
__device__ __half g_w216 [FF * E_];
__device__ __half g_qkv16[NROWS * 3 * E_];  // Q|K|V fp16
__device__ __half g_attn16[NROWS * E_];     // attention out fp16
__device__ float  g_x1   [NROWS * E_];      // residual 1 (fp32)
__device__ __half g_h2_16[NROWS * E_];      // LN2 output fp16
__device__ __half g_ff116[NROWS * FF];      // FFN hidden fp16

__device__ __forceinline__ void cp_async16(uint32_t dst, const void* src) {
    asm volatile("cp.async.cg.shared.global [%0], [%1], 16;" :: "r"(dst), "l"(src));
}
__device__ __forceinline__ uint32_t smem_u32(const void* p) {
    uint32_t a;
    asm("{ .reg .u64 t; cvta.to.shared.u64 t, %1; cvt.u32.u64 %0, t; }" : "=r"(a) : "l"(p));
    return a;
}
// D += A*B, m16n8k16 fp16 inputs, fp32 accum
__device__ __forceinline__ void mma16(float* c, const uint32_t* a, uint32_t b0, uint32_t b1) {
    asm volatile("mma.sync.aligned.m16n8k16.row.col.f32.f16.f16.f32 "
        "{%0,%1,%2,%3}, {%4,%5,%6,%7}, {%8,%9}, {%0,%1,%2,%3};"
        : "+f"(c[0]), "+f"(c[1]), "+f"(c[2]), "+f"(c[3])
        : "r"(a[0]), "r"(a[1]), "r"(a[2]), "r"(a[3]), "r"(b0), "r"(b1));
}
__device__ __forceinline__ void ldsm4(uint32_t* r, uint32_t a) {
    asm volatile("ldmatrix.sync.aligned.m8n8.x4.shared.b16 {%0,%1,%2,%3}, [%4];"
        : "=r"(r[0]), "=r"(r[1]), "=r"(r[2]), "=r"(r[3]) : "r"(a));
}
__device__ __forceinline__ void ldsm4t(uint32_t* r, uint32_t a) {
    asm volatile("ldmatrix.sync.aligned.m8n8.x4.trans.shared.b16 {%0,%1,%2,%3}, [%4];"
        : "=r"(r[0]), "=r"(r[1]), "=r"(r[2]), "=r"(r[3]) : "r"(a));
}

// ---------------- LayerNorm (fp32 in -> fp16 out) ----------------------------
__global__ __launch_bounds__(256) void ln_kernel(const float* __restrict__ x,
                                                 const float* __restrict__ g,
                                                 const float* __restrict__ b,
                                                 __half* __restrict__ out)
{
    int row = blockIdx.x;
    int tid = threadIdx.x;
    const float4* xr = reinterpret_cast<const float4*>(x + (size_t)row * E_);
    float4 v = xr[tid];
    float s  = v.x + v.y + v.z + v.w;
    float sq = v.x*v.x + v.y*v.y + v.z*v.z + v.w*v.w;

    __shared__ float sh[16];
    __shared__ float s_mu, s_rs;
    #pragma unroll
    for (int o = 16; o > 0; o >>= 1) {
        s  += __shfl_down_sync(0xffffffffu, s,  o);
        sq += __shfl_down_sync(0xffffffffu, sq, o);
    }
    int lane = tid & 31, wid = tid >> 5;
    if (lane == 0) { sh[wid] = s; sh[8 + wid] = sq; }
    __syncthreads();
    if (tid == 0) {
        float ts = 0.f, tq = 0.f;
        #pragma unroll
        for (int w = 0; w < 8; w++) { ts += sh[w]; tq += sh[8 + w]; }
        float mu  = ts * (1.0f / E_);
        float var = tq * (1.0f / E_) - mu * mu;
        s_mu = mu;
        s_rs = rsqrtf(var + 1e-5f);
    }
    __syncthreads();
    float mu = s_mu, rs = s_rs;
    float4 gg = reinterpret_cast<const float4*>(g)[tid];
    float4 bb = reinterpret_cast<const float4*>(b)[tid];
    __half2 h0 = __floats2half2_rn((v.x - mu) * rs * gg.x + bb.x,
                                   (v.y - mu) * rs * gg.y + bb.y);
    __half2 h1 = __floats2half2_rn((v.z - mu) * rs * gg.z + bb.z,
                                   (v.w - mu) * rs * gg.w + bb.w);
    __half2* op = reinterpret_cast<__half2*>(out + (size_t)row * E_ + tid * 4);
    op[0] = h0; op[1] = h1;
}

// ---------------- fused prep: repack QKV + f2h of Wp/W1/W2 -------------------
__device__ __forceinline__ void cvt8(const float* ip, __half* op) {
    const float4* p = reinterpret_cast<const float4*>(ip);
    float4 a = p[0], b = p[1];
    __half2 h[4] = { __floats2half2_rn(a.x, a.y), __floats2half2_rn(a.z, a.w),
                     __floats2half2_rn(b.x, b.y), __floats2half2_rn(b.z, b.w) };
    *reinterpret_cast<float4*>(op) = *reinterpret_cast<float4*>(h);
}
#define RP4  (H_ * E_ * HS_ / 4)      // repack work items (4 elems each)
__global__ void prep_kernel(const float* __restrict__ Wq, const float* __restrict__ Wk,
                            const float* __restrict__ Wv, __half* __restrict__ Wqkv,
                            const float* __restrict__ Wp, __half* __restrict__ wp16,
                            const float* __restrict__ W1, __half* __restrict__ w116,
                            const float* __restrict__ W2, __half* __restrict__ w216)
{
    int i = blockIdx.x * blockDim.x + threadIdx.x;
    if (i < RP4) {
        int h = i / (E_ * HS_ / 4);
        int r = i % (E_ * HS_ / 4);
        int e = r / (HS_ / 4);
        int d4 = (r % (HS_ / 4)) * 4;
        int col = h * HS_ + d4;
        size_t base = (size_t)e * (3 * E_);
        size_t src = (size_t)i * 4;
        float4 q = *reinterpret_cast<const float4*>(Wq + src);
        float4 k = *reinterpret_cast<const float4*>(Wk + src);
        float4 v = *reinterpret_cast<const float4*>(Wv + src);
        __half2 qh[2] = { __floats2half2_rn(q.x, q.y), __floats2half2_rn(q.z, q.w) };
        __half2 kh[2] = { __floats2half2_rn(k.x, k.y), __floats2half2_rn(k.z, k.w) };
        __half2 vh[2] = { __floats2half2_rn(v.x, v.y), __floats2half2_rn(v.z, v.w) };
        *reinterpret_cast<float2*>(Wqkv + base + col)           = *reinterpret_cast<float2*>(qh);
        *reinterpret_cast<float2*>(Wqkv + base + E_ + col)      = *reinterpret_cast<float2*>(kh);
        *reinterpret_cast<float2*>(Wqkv + base + 2 * E_ + col)  = *reinterpret_cast<float2*>(vh);
        return;
    }
    int j = i - RP4;                              // 8-elem convert items
    int na8 = E_ * E_ / 8, nb8 = E_ * FF / 8, nc8 = FF * E_ / 8;
    if (j < na8)      { cvt8(Wp + 8 * (size_t)j, wp16 + 8 * (size_t)j); return; }
    j -= na8;
    if (j < nb8)      { cvt8(W1 + 8 * (size_t)j, w116 + 8 * (size_t)j); return; }
    j -= nb8;
    if (j < nc8)      { cvt8(W2 + 8 * (size_t)j, w216 + 8 * (size_t)j); }
}

// ---------------- fp16 WMMA GEMM (m16n16k16, fp32 accum, BK=64) --------------
// best-known config: 128 threads / 4 warps, warp tile 64x64, 3-stage cp.async.
#define BM   128
#define BN   128
#define BKC  64
#define ASTH 72
#define BSTH 136
#define STAGE_H (BM*ASTH + BKC*BSTH)
#define NSTG 3
#define CST  132
#define GSMEM (NSTG * STAGE_H * 2)

__global__ __launch_bounds__(128, 2) void h16_gemm(
    const __half* __restrict__ A, const __half* __restrict__ Bm,
    float* __restrict__ C, __half* __restrict__ Ch, int M, int N, int K,
    const float* __restrict__ bias, const float* __restrict__ res, int relu)
{
    extern __shared__ float sm[];
    __half* smh = reinterpret_cast<__half*>(sm);
    uint32_t smb = smem_u32(sm);

    int tid  = threadIdx.x;
    int wid  = tid >> 5;
    int wm   = wid & 1;
    int wn   = wid >> 1;
    int m0   = blockIdx.y * BM;
    int n0   = blockIdx.x * BN;
    int NC   = K / BKC;

    wmma::fragment<wmma::accumulator, 16, 16, 16, float> acc[4][4];
    #pragma unroll
    for (int i = 0; i < 4; i++)
        #pragma unroll
        for (int j = 0; j < 4; j++)
            wmma::fill_fragment(acc[i][j], 0.0f);

    auto issue = [&](int c) {
        int buf = c % NSTG;
        uint32_t stA = smb + (uint32_t)(buf * STAGE_H) * 2u;
        uint32_t stB = stA + (uint32_t)(BM * ASTH) * 2u;
        int k0 = c * BKC;
        #pragma unroll
        for (int t = 0; t < 8; t++) {
            int idx = tid + t * 128;
            int r  = idx >> 3;
            int kk = (idx & 7) * 8;
            cp_async16(stA + (uint32_t)(r * ASTH + kk) * 2u,
                       A + (size_t)(m0 + r) * K + k0 + kk);
        }
        #pragma unroll
        for (int t = 0; t < 8; t++) {
            int idx = tid + t * 128;
            int r  = idx >> 4;
            int nn = (idx & 15) * 8;
            cp_async16(stB + (uint32_t)(r * BSTH + nn) * 2u,
                       Bm + (size_t)(k0 + r) * N + n0 + nn);
        }
        asm volatile("cp.async.commit_group;" ::: "memory");
    };

    issue(0);
    if (NC > 1) issue(1);

    for (int c = 0; c < NC; c++) {
        if (c + 2 < NC) {
            issue(c + 2);
            asm volatile("cp.async.wait_group 2;" ::: "memory");
        } else if (c + 1 < NC) {
            asm volatile("cp.async.wait_group 1;" ::: "memory");
        } else {
            asm volatile("cp.async.wait_group 0;" ::: "memory");
        }
        __syncthreads();

        const __half* sA = smh + (c % NSTG) * STAGE_H;
        const __half* sB = sA + BM * ASTH;

        #pragma unroll
        for (int kk = 0; kk < 4; kk++) {
            wmma::fragment<wmma::matrix_a, 16, 16, 16, __half, wmma::row_major> af[4];
            wmma::fragment<wmma::matrix_b, 16, 16, 16, __half, wmma::row_major> bf[4];
            #pragma unroll
            for (int i = 0; i < 4; i++)
                wmma::load_matrix_sync(af[i], sA + (wm * 64 + i * 16) * ASTH + kk * 16, ASTH);
            #pragma unroll
            for (int j = 0; j < 4; j++)
                wmma::load_matrix_sync(bf[j], sB + (kk * 16) * BSTH + wn * 64 + j * 16, BSTH);
            #pragma unroll
            for (int i = 0; i < 4; i++)
                #pragma unroll
                for (int j = 0; j < 4; j++)
                    wmma::mma_sync(acc[i][j], af[i], bf[j], acc[i][j]);
        }
        __syncthreads();
    }

    float* Cs = sm;
    #pragma unroll
    for (int i = 0; i < 4; i++)
        #pragma unroll
        for (int j = 0; j < 4; j++)
            wmma::store_matrix_sync(Cs + (wm * 64 + i * 16) * CST + wn * 64 + j * 16,
                                    acc[i][j], CST, wmma::mem_row_major);
    __syncthreads();

    for (int idx = tid; idx < BM * BN / 4; idx += 128) {
        int r  = idx >> 5;
        int c4 = idx & 31;
        float4 v = *reinterpret_cast<const float4*>(Cs + r * CST + c4 * 4);
        int col = n0 + c4 * 4;
        size_t row = (size_t)(m0 + r);
        if (bias) {
            float4 bb = *reinterpret_cast<const float4*>(bias + col);
            v.x += bb.x; v.y += bb.y; v.z += bb.z; v.w += bb.w;
        }
        if (relu) {
            v.x = fmaxf(v.x, 0.f); v.y = fmaxf(v.y, 0.f);
            v.z = fmaxf(v.z, 0.f); v.w = fmaxf(v.w, 0.f);
        }
        if (res) {
            float4 rr = *reinterpret_cast<const float4*>(res + row * N + col);
            v.x += rr.x; v.y += rr.y; v.z += rr.z; v.w += rr.w;
        }
        if (Ch) {
            __half2* hp = reinterpret_cast<__half2*>(Ch + row * N + col);
            hp[0] = __floats2half2_rn(v.x, v.y);
            hp[1] = __floats2half2_rn(v.z, v.w);
        } else {
            *reinterpret_cast<float4*>(C + row * N + col) = v;
        }
    }
}

// ---------------- fp16 tensor-core causal flash attention --------------------
// 128 threads = 4 warps; q-block 64 rows; register P; ldmatrix K/V; exp2 softmax.
// m-reduction packed in half2 (m cancels in softmax; only needs quad consistency);
// l kept as per-thread quad-partials, reduced once at the end.
#define APH 72

__global__ __launch_bounds__(128) void attn_kernel(const __half* __restrict__ qkv,
                                                   __half* __restrict__ out)
{
    __shared__ __half asm16[4 * 64 * APH];
    uint32_t smu = smem_u32(asm16);

    int tid = threadIdx.x, w = tid >> 5, lane = tid & 31;
    int gid = lane >> 2, tig = lane & 3;
    int g8  = lane >> 3, i8 = lane & 7;
    int qt = (T_ / 64 - 1) - blockIdx.x;
    int bh = blockIdx.y, b = bh >> 4, h = bh & 15;

    int rowK = ((g8 >> 1) << 3) + i8;
    int colK = (g8 & 1) << 3;
    int rowV = ((g8 & 1) << 3) + i8;
    int colV = (g8 >> 1) << 3;

    // Q scaled by HS^-1/2 * log2(e): softmax computed in base 2 throughout.
    uint32_t qa[4][4];
    {
        const __half2 sc2 = __floats2half2_rn(0.18033688f, 0.18033688f);  // 0.125*log2(e)
        #pragma unroll
        for (int ks = 0; ks < 4; ks++)
            #pragma unroll
            for (int r = 0; r < 4; r++) {
                int row = w * 16 + gid + (r & 1) * 8;
                int col = ks * 16 + 2 * tig + ((r >> 1) * 8);
                __half2 v = *reinterpret_cast<const __half2*>(
                    qkv + (size_t)(b * T_ + qt * 64 + row) * (3 * E_) + h * HS_ + col);
                v = __hmul2(v, sc2);
                qa[ks][r] = *reinterpret_cast<uint32_t*>(&v);
            }
    }

    float oa[8][4];
    #pragma unroll
    for (int nt = 0; nt < 8; nt++)
        #pragma unroll
        for (int r = 0; r < 4; r++) oa[nt][r] = 0.f;
    float m0 = -1e30f, m1 = -1e30f, l0 = 0.f, l1 = 0.f;   // l: quad-partial

    auto loadKV = [&](int kt, int bu) {
        const __half* kb = qkv + (size_t)(b * T_ + kt * 64) * (3 * E_) + E_ + h * HS_;
        const __half* vb = kb + E_;
        uint32_t kbase = smu + (uint32_t)(bu * 64 * APH) * 2u;
        uint32_t vbase = smu + (uint32_t)((2 + bu) * 64 * APH) * 2u;
        #pragma unroll
        for (int t = 0; t < 4; t++) {
            int i = tid + t * 128;
            int r = i >> 3, c = (i & 7) * 8;
            cp_async16(kbase + (uint32_t)(r * APH + c) * 2u, kb + (size_t)r * (3 * E_) + c);
            cp_async16(vbase + (uint32_t)(r * APH + c) * 2u, vb + (size_t)r * (3 * E_) + c);
        }
        asm volatile("cp.async.commit_group;" ::: "memory");
    };

    loadKV(0, 0);

    for (int kt = 0; kt <= qt; kt++) {
        int bu = kt & 1;
        if (kt < qt) {
            loadKV(kt + 1, bu ^ 1);
            asm volatile("cp.async.wait_group 1;" ::: "memory");
        } else {
            asm volatile("cp.async.wait_group 0;" ::: "memory");
        }
        __syncthreads();

        uint32_t kbase = smu + (uint32_t)(bu * 64 * APH) * 2u;
        uint32_t vbase = smu + (uint32_t)((2 + bu) * 64 * APH) * 2u;

        float sa[8][4];
        #pragma unroll
        for (int nt = 0; nt < 8; nt++)
            #pragma unroll
            for (int r = 0; r < 4; r++) sa[nt][r] = 0.f;

        #pragma unroll
        for (int ks = 0; ks < 4; ks++) {
            #pragma unroll
            for (int ntp = 0; ntp < 4; ntp++) {
                uint32_t kf[4];
                ldsm4(kf, kbase + (uint32_t)((ntp * 16 + rowK) * APH + ks * 16 + colK) * 2u);
                mma16(sa[2 * ntp],     qa[ks], kf[0], kf[1]);
                mma16(sa[2 * ntp + 1], qa[ks], kf[2], kf[3]);
            }
        }

        if (kt == qt) {
            int r0 = w * 16 + gid, r1 = r0 + 8;
            #pragma unroll
            for (int nt = 0; nt < 8; nt++) {
                int c0 = nt * 8 + 2 * tig, c1 = c0 + 1;
                if (c0 > r0) sa[nt][0] = -1e30f;
                if (c1 > r0) sa[nt][1] = -1e30f;
                if (c0 > r1) sa[nt][2] = -1e30f;
                if (c1 > r1) sa[nt][3] = -1e30f;
            }
        }

        // ---- row-max: thread-local fp32, quad-reduce packed in half2 ----
        float mt0 = -1e30f, mt1 = -1e30f;
        #pragma unroll
        for (int nt = 0; nt < 8; nt++) {
            mt0 = fmaxf(mt0, fmaxf(sa[nt][0], sa[nt][1]));
            mt1 = fmaxf(mt1, fmaxf(sa[nt][2], sa[nt][3]));
        }
        {
            __half2 mh = __floats2half2_rn(mt0, mt1);
            uint32_t mu_ = *reinterpret_cast<uint32_t*>(&mh);
            uint32_t o1 = __shfl_xor_sync(0xffffffffu, mu_, 1);
            mh = __hmax2(mh, *reinterpret_cast<__half2*>(&o1));
            mu_ = *reinterpret_cast<uint32_t*>(&mh);
            uint32_t o2 = __shfl_xor_sync(0xffffffffu, mu_, 2);
            mh = __hmax2(mh, *reinterpret_cast<__half2*>(&o2));
            float2 mf = __half22float2(mh);
            mt0 = mf.x; mt1 = mf.y;
        }

        float mn0 = fmaxf(m0, mt0), mn1 = fmaxf(m1, mt1);
        float cr0 = exp2f(m0 - mn0), cr1 = exp2f(m1 - mn1);
        m0 = mn0; m1 = mn1;

        float s0 = 0.f, s1 = 0.f;
        uint32_t ph0[8], ph1[8];
        #pragma unroll
        for (int nt = 0; nt < 8; nt++) {
            float e0 = exp2f(sa[nt][0] - mn0), e1 = exp2f(sa[nt][1] - mn0);
            float e2 = exp2f(sa[nt][2] - mn1), e3 = exp2f(sa[nt][3] - mn1);
            s0 += e0 + e1;  s1 += e2 + e3;
            __half2 hp0 = __floats2half2_rn(e0, e1);
            __half2 hp1 = __floats2half2_rn(e2, e3);
            ph0[nt] = *reinterpret_cast<uint32_t*>(&hp0);
            ph1[nt] = *reinterpret_cast<uint32_t*>(&hp1);
        }
        // l stays quad-partial; reduced after the loop
        l0 = l0 * cr0 + s0;
        l1 = l1 * cr1 + s1;

        #pragma unroll
        for (int nt = 0; nt < 8; nt++) {
            oa[nt][0] *= cr0; oa[nt][1] *= cr0;
            oa[nt][2] *= cr1; oa[nt][3] *= cr1;
        }

        #pragma unroll
        for (int ks = 0; ks < 4; ks++) {
            uint32_t pa[4] = { ph0[2 * ks], ph1[2 * ks], ph0[2 * ks + 1], ph1[2 * ks + 1] };
            #pragma unroll
            for (int ntp = 0; ntp < 4; ntp++) {
                uint32_t vf[4];
                ldsm4t(vf, vbase + (uint32_t)((ks * 16 + rowV) * APH + ntp * 16 + colV) * 2u);
                mma16(oa[2 * ntp],     pa, vf[0], vf[1]);
                mma16(oa[2 * ntp + 1], pa, vf[2], vf[3]);
            }
        }
        __syncthreads();
    }

    // ---- final l quad-reduction, then normalize & store ----
    l0 += __shfl_xor_sync(0xffffffffu, l0, 1);
    l0 += __shfl_xor_sync(0xffffffffu, l0, 2);
    l1 += __shfl_xor_sync(0xffffffffu, l1, 1);
    l1 += __shfl_xor_sync(0xffffffffu, l1, 2);

    float i0 = 1.f / l0, i1 = 1.f / l1;
    int r0 = qt * 64 + w * 16 + gid;
    #pragma unroll
    for (int nt = 0; nt < 8; nt++) {
        int col = h * HS_ + nt * 8 + 2 * tig;
        __half2* p0 = reinterpret_cast<__half2*>(out + (size_t)(b * T_ + r0) * E_ + col);
        __half2* p1 = reinterpret_cast<__half2*>(out + (size_t)(b * T_ + r0 + 8) * E_ + col);
        *p0 = __floats2half2_rn(oa[nt][0] * i0, oa[nt][1] * i0);
        *p1 = __floats2half2_rn(oa[nt][2] * i1, oa[nt][3] * i1);
    }
}

// ---------------- host -------------------------------------------------------
extern "C" void kernel_launch(void* const* d_in, const int* in_sizes, int n_in,
                              void* d_out, int out_size)
{
    const float* x   = (const float*)d_in[0];
    const float* Wq  = (const float*)d_in[1];
    const float* Wk  = (const float*)d_in[2];
    const float* Wv  = (const float*)d_in[3];
    const float* Wp  = (const float*)d_in[4];
    const float* bp  = (const float*)d_in[5];
    const float* W1  = (const float*)d_in[6];
    const float* b1  = (const float*)d_in[7];
    const float* W2  = (const float*)d_in[8];
    const float* b2  = (const float*)d_in[9];
    const float* g1  = (const float*)d_in[10];
    const float* be1 = (const float*)d_in[11];
    const float* g2  = (const float*)d_in[12];
    const float* be2 = (const float*)d_in[13];
    float* out = (float*)d_out;

    __half *h16, *wqkv16, *wp16, *w116, *w216, *qkv16, *attn16, *h2_16, *ff116;
    float *x1;
    cudaGetSymbolAddress((void**)&h16,    g_h16);
    cudaGetSymbolAddress((void**)&wqkv16, g_wqkv16);
    cudaGetSymbolAddress((void**)&wp16,   g_wp16);
    cudaGetSymbolAddress((void**)&w116,   g_w116);
    cudaGetSymbolAddress((void**)&w216,   g_w216);
    cudaGetSymbolAddress((void**)&qkv16,  g_qkv16);
    cudaGetSymbolAddress((void**)&attn16, g_attn16);
    cudaGetSymbolAddress((void**)&x1,     g_x1);
    cudaGetSymbolAddress((void**)&h2_16,  g_h2_16);
    cudaGetSymbolAddress((void**)&ff116,  g_ff116);

    cudaFuncSetAttribute(h16_gemm, cudaFuncAttributeMaxDynamicSharedMemorySize, GSMEM);

    // prep: LN1 + single fused weight-prep kernel
    ln_kernel<<<NROWS, 256>>>(x, g1, be1, h16);
    {
        int total = RP4 + E_ * E_ / 8 + E_ * FF / 8 + FF * E_ / 8;
        prep_kernel<<<(total + 255) / 256, 256>>>(Wq, Wk, Wv, wqkv16,
                                                  Wp, wp16, W1, w116, W2, w216);
    }

    // QKV = h @ Wqkv -> fp16
    h16_gemm<<<dim3(3*E_/BN, NROWS/BM), 128, GSMEM>>>(
        h16, wqkv16, nullptr, qkv16, NROWS, 3*E_, E_, nullptr, nullptr, 0);
    // attention (fp16 tensor cores, register-resident P, exp2 softmax) -> fp16
    attn_kernel<<<dim3(T_/64, B_*H_), 128>>>(qkv16, attn16);
    // x1 = x + attn @ Wp + bp  (fp32 out)
    h16_gemm<<<dim3(E_/BN, NROWS/BM), 128, GSMEM>>>(
        attn16, wp16, x1, nullptr, NROWS, E_, E_, bp, x, 0);
    // h2 = LN2(x1) -> fp16
    ln_kernel<<<NROWS, 256>>>(x1, g2, be2, h2_16);
    // ff1 = relu(h2 @ W1 + b1) -> fp16
    h16_gemm<<<dim3(FF/BN, NROWS/BM), 128, GSMEM>>>(
        h2_16, w116, nullptr, ff116, NROWS, FF, E_, b1, nullptr, 1);
    // out = x1 + ff1 @ W2 + b2  (fp32 out, K = 4096)
    h16_gemm<<<dim3(E_/BN, NROWS/BM), 128, GSMEM>>>(
        ff116, w216, out, nullptr, NROWS, E_, FF, b2, x1, 0);
}